// round 3
// baseline (speedup 1.0000x reference)
#include <cuda_runtime.h>

// Problem shape (fixed by dataset)
#define B_  2
#define T_  2048
#define C_  1024
#define H_  16
#define HD_ 64
#define NI_ 3
#define M_  (B_ * T_)          // 4096 rows for all projection GEMMs
#define NEG_ (-1e9f)

// -------- scratch (device globals; no allocation allowed) --------
__device__ float g_Q[(size_t)M_ * C_];
__device__ float g_K[(size_t)M_ * C_];
__device__ float g_V[(size_t)M_ * C_];
__device__ float g_O[(size_t)M_ * C_];

// ============================================================================
// Tiled fp32 GEMM: C = sum_{n<nmat} A_n[M,K] @ B_n[K,N]  + sum_n bias_n[N]
// A matrices strided by strideA, B by K*N, bias by N.
// BM=BN=128, BK=16, 256 threads, 8x8 per-thread microtile.
// All of M,N,K are multiples of tile dims in this problem -> no guards.
// ============================================================================
#define GBM 128
#define GBN 128
#define GBK 16

__global__ __launch_bounds__(256) void gemm_bias_kernel(
    const float* __restrict__ A, const float* __restrict__ Bm,
    const float* __restrict__ bias, float* __restrict__ C,
    int M, int N, int K, int nmat, size_t strideA)
{
    __shared__ float As[GBK][GBM];   // transposed A tile
    __shared__ float Bs[GBK][GBN];

    const int tid = threadIdx.x;
    const int bm = blockIdx.y * GBM;
    const int bn = blockIdx.x * GBN;
    const int tx = tid & 15;         // 0..15
    const int ty = tid >> 4;         // 0..15

    float acc[8][8];
    #pragma unroll
    for (int i = 0; i < 8; i++)
        #pragma unroll
        for (int j = 0; j < 8; j++) acc[i][j] = 0.f;

    for (int n = 0; n < nmat; n++) {
        const float* An = A  + (size_t)n * strideA;
        const float* Bn = Bm + (size_t)n * K * N;
        for (int k0 = 0; k0 < K; k0 += GBK) {
            // Load A tile (128x16) as 512 float4s, store transposed
            #pragma unroll
            for (int v = 0; v < 2; v++) {
                int idx = tid + v * 256;       // 0..511
                int row = idx >> 2;            // 0..127
                int kc  = (idx & 3) << 2;      // 0,4,8,12
                float4 a = *(const float4*)&An[(size_t)(bm + row) * K + k0 + kc];
                As[kc + 0][row] = a.x;
                As[kc + 1][row] = a.y;
                As[kc + 2][row] = a.z;
                As[kc + 3][row] = a.w;
            }
            // Load B tile (16x128) as 512 float4s
            #pragma unroll
            for (int v = 0; v < 2; v++) {
                int idx = tid + v * 256;
                int kr = idx >> 5;             // 0..15
                int nc = (idx & 31) << 2;      // 0..124
                *(float4*)&Bs[kr][nc] =
                    *(const float4*)&Bn[(size_t)(k0 + kr) * N + bn + nc];
            }
            __syncthreads();

            #pragma unroll
            for (int kk = 0; kk < GBK; kk++) {
                float4 a0 = *(float4*)&As[kk][ty * 8];
                float4 a1 = *(float4*)&As[kk][ty * 8 + 4];
                float4 b0 = *(float4*)&Bs[kk][tx * 8];
                float4 b1 = *(float4*)&Bs[kk][tx * 8 + 4];
                float ar[8] = {a0.x, a0.y, a0.z, a0.w, a1.x, a1.y, a1.z, a1.w};
                float br[8] = {b0.x, b0.y, b0.z, b0.w, b1.x, b1.y, b1.z, b1.w};
                #pragma unroll
                for (int i = 0; i < 8; i++)
                    #pragma unroll
                    for (int j = 0; j < 8; j++)
                        acc[i][j] += ar[i] * br[j];
            }
            __syncthreads();
        }
    }

    // Epilogue: summed bias add
    #pragma unroll
    for (int i = 0; i < 8; i++) {
        int row = bm + ty * 8 + i;
        #pragma unroll
        for (int j = 0; j < 8; j += 4) {
            int col = bn + tx * 8 + j;
            float bsum0 = 0.f, bsum1 = 0.f, bsum2 = 0.f, bsum3 = 0.f;
            for (int n = 0; n < nmat; n++) {
                bsum0 += bias[n * N + col + 0];
                bsum1 += bias[n * N + col + 1];
                bsum2 += bias[n * N + col + 2];
                bsum3 += bias[n * N + col + 3];
            }
            float4 r;
            r.x = acc[i][j + 0] + bsum0;
            r.y = acc[i][j + 1] + bsum1;
            r.z = acc[i][j + 2] + bsum2;
            r.w = acc[i][j + 3] + bsum3;
            *(float4*)&C[(size_t)row * N + col] = r;
        }
    }
}

// ============================================================================
// Flash attention with post-softmax distance modulation.
//   out_t = ( sum_s e^{x_ts - m} * w_ts * v_s ) / ( sum_s e^{x_ts - m} )
// Grid: (B*H, T1/64). Block: 256 threads. 64x64 tiles, hd=64.
// Dynamic smem: Qt/Kt transposed [64][68], Vs [64][68], S [64][65], stats.
// ============================================================================
#define FBR 64
#define FBC 64
#define QSTRIDE 68
#define SSTRIDE 65
#define FLASH_SMEM ((3 * 64 * QSTRIDE + 64 * SSTRIDE + 3 * 64) * 4)

__global__ __launch_bounds__(256) void flash_kernel(
    const float* __restrict__ Q, const float* __restrict__ Kg,
    const float* __restrict__ Vg, const int* __restrict__ mask,
    const float* __restrict__ dist, float* __restrict__ O)
{
    extern __shared__ float sm[];
    float* Qt   = sm;                      // [64][68] : Qt[d][i]
    float* Kt   = Qt + 64 * QSTRIDE;       // [64][68] : Kt[d][j]
    float* Vs   = Kt + 64 * QSTRIDE;       // [64][68] : Vs[s][c]
    float* Ssm  = Vs + 64 * QSTRIDE;       // [64][65]
    float* mrow = Ssm + 64 * SSTRIDE;      // [64]
    float* lrow = mrow + 64;               // [64]
    float* frow = lrow + 64;               // [64]

    const int bh  = blockIdx.x;            // 0..31
    const int b   = bh >> 4;
    const int h   = bh & 15;
    const int t10 = blockIdx.y * FBR;
    const int tid = threadIdx.x;
    const int tx  = tid & 15;
    const int ty  = tid >> 4;

    // ---- load Q tile, transposed into Qt[d][i] ----
    {
        int i  = tid >> 2;                 // 0..63
        int d0 = (tid & 3) << 4;           // 0,16,32,48
        const float* qp = &Q[((size_t)(b * T_ + t10 + i)) * C_ + h * HD_ + d0];
        #pragma unroll
        for (int v = 0; v < 4; v++) {
            float4 q4 = *(const float4*)(qp + v * 4);
            Qt[(d0 + v * 4 + 0) * QSTRIDE + i] = q4.x;
            Qt[(d0 + v * 4 + 1) * QSTRIDE + i] = q4.y;
            Qt[(d0 + v * 4 + 2) * QSTRIDE + i] = q4.z;
            Qt[(d0 + v * 4 + 3) * QSTRIDE + i] = q4.w;
        }
    }
    if (tid < 64) { mrow[tid] = -3.0e38f; lrow[tid] = 0.f; }

    float o[4][4];
    #pragma unroll
    for (int i = 0; i < 4; i++)
        #pragma unroll
        for (int j = 0; j < 4; j++) o[i][j] = 0.f;

    __syncthreads();

    for (int s0 = 0; s0 < T_; s0 += FBC) {
        // ---- load K (transposed) and V (direct) ----
        {
            int j  = tid >> 2;
            int d0 = (tid & 3) << 4;
            const float* kp = &Kg[((size_t)(b * T_ + s0 + j)) * C_ + h * HD_ + d0];
            #pragma unroll
            for (int v = 0; v < 4; v++) {
                float4 k4 = *(const float4*)(kp + v * 4);
                Kt[(d0 + v * 4 + 0) * QSTRIDE + j] = k4.x;
                Kt[(d0 + v * 4 + 1) * QSTRIDE + j] = k4.y;
                Kt[(d0 + v * 4 + 2) * QSTRIDE + j] = k4.z;
                Kt[(d0 + v * 4 + 3) * QSTRIDE + j] = k4.w;
            }
            const float* vp = &Vg[((size_t)(b * T_ + s0 + j)) * C_ + h * HD_ + d0];
            #pragma unroll
            for (int v = 0; v < 4; v++)
                *(float4*)&Vs[j * QSTRIDE + d0 + v * 4] =
                    *(const float4*)(vp + v * 4);
        }
        __syncthreads();

        // ---- S = (Q K^T) * scale ----
        float sacc[4][4];
        #pragma unroll
        for (int i = 0; i < 4; i++)
            #pragma unroll
            for (int j = 0; j < 4; j++) sacc[i][j] = 0.f;

        #pragma unroll 8
        for (int d = 0; d < HD_; d++) {
            float4 qv = *(float4*)&Qt[d * QSTRIDE + ty * 4];
            float4 kv = *(float4*)&Kt[d * QSTRIDE + tx * 4];
            float qa[4] = {qv.x, qv.y, qv.z, qv.w};
            float ka[4] = {kv.x, kv.y, kv.z, kv.w};
            #pragma unroll
            for (int i = 0; i < 4; i++)
                #pragma unroll
                for (int j = 0; j < 4; j++)
                    sacc[i][j] += qa[i] * ka[j];
        }
        #pragma unroll
        for (int i = 0; i < 4; i++)
            #pragma unroll
            for (int j = 0; j < 4; j++)
                Ssm[(ty * 4 + i) * SSTRIDE + tx * 4 + j] = sacc[i][j] * 0.125f;
        __syncthreads();

        // ---- mask (coalesced over s) ----
        #pragma unroll
        for (int e = tid; e < FBR * FBC; e += 256) {
            int r = e >> 6, s = e & 63;
            int mk = mask[((size_t)b * T_ + t10 + r) * T_ + s0 + s];
            if (mk == 0) Ssm[r * SSTRIDE + s] = NEG_;
        }
        __syncthreads();

        // ---- per-row online-softmax stats; overwrite S with exp ----
        if (tid < 64) {
            int r = tid;
            float mt = -3.0e38f;
            #pragma unroll 8
            for (int s = 0; s < FBC; s++)
                mt = fmaxf(mt, Ssm[r * SSTRIDE + s]);
            float m_old = mrow[r];
            float m_new = fmaxf(m_old, mt);
            float fr = __expf(m_old - m_new);
            float sum = 0.f;
            #pragma unroll 8
            for (int s = 0; s < FBC; s++) {
                float e = __expf(Ssm[r * SSTRIDE + s] - m_new);
                Ssm[r * SSTRIDE + s] = e;
                sum += e;
            }
            lrow[r] = lrow[r] * fr + sum;
            mrow[r] = m_new;
            frow[r] = fr;
        }
        __syncthreads();

        // ---- numerator-only distance modulation (coalesced) ----
        #pragma unroll
        for (int e = tid; e < FBR * FBC; e += 256) {
            int r = e >> 6, s = e & 63;
            float d = dist[((size_t)b * T_ + t10 + r) * T_ + s0 + s];
            Ssm[r * SSTRIDE + s] *= __expf(-4.0f * d * d);  // GAMMA = 0.5
        }
        __syncthreads();

        // ---- rescale O, accumulate P @ V ----
        #pragma unroll
        for (int i = 0; i < 4; i++) {
            float fr = frow[ty * 4 + i];
            #pragma unroll
            for (int j = 0; j < 4; j++) o[i][j] *= fr;
        }
        #pragma unroll 4
        for (int s = 0; s < FBC; s++) {
            float4 vv = *(float4*)&Vs[s * QSTRIDE + tx * 4];
            float va[4] = {vv.x, vv.y, vv.z, vv.w};
            float p0 = Ssm[(ty * 4 + 0) * SSTRIDE + s];
            float p1 = Ssm[(ty * 4 + 1) * SSTRIDE + s];
            float p2 = Ssm[(ty * 4 + 2) * SSTRIDE + s];
            float p3 = Ssm[(ty * 4 + 3) * SSTRIDE + s];
            #pragma unroll
            for (int j = 0; j < 4; j++) {
                o[0][j] += p0 * va[j];
                o[1][j] += p1 * va[j];
                o[2][j] += p2 * va[j];
                o[3][j] += p3 * va[j];
            }
        }
        __syncthreads();
    }

    // ---- epilogue: divide by denominator, write [B,T1,C] layout ----
    #pragma unroll
    for (int i = 0; i < 4; i++) {
        float inv = 1.0f / lrow[ty * 4 + i];
        float4 ov;
        ov.x = o[i][0] * inv;
        ov.y = o[i][1] * inv;
        ov.z = o[i][2] * inv;
        ov.w = o[i][3] * inv;
        *(float4*)&O[((size_t)(b * T_ + t10 + ty * 4 + i)) * C_ +
                     h * HD_ + tx * 4] = ov;
    }
}

// ============================================================================
// Launch
// ============================================================================
extern "C" void kernel_launch(void* const* d_in, const int* in_sizes, int n_in,
                              void* d_out, int out_size)
{
    const float* x_q  = (const float*)d_in[0];
    const float* x_r  = (const float*)d_in[1];
    const float* y    = (const float*)d_in[2];
    const int*   mask = (const int*)  d_in[3];
    const float* dist = (const float*)d_in[4];
    const float* Wq   = (const float*)d_in[5];
    const float* bq   = (const float*)d_in[6];
    const float* Wk   = (const float*)d_in[7];
    const float* bk   = (const float*)d_in[8];
    const float* Wv   = (const float*)d_in[9];
    const float* bv   = (const float*)d_in[10];
    const float* Wp   = (const float*)d_in[11];
    const float* bp   = (const float*)d_in[12];
    float* out = (float*)d_out;

    float *Qb, *Kb, *Vb, *Ob;
    cudaGetSymbolAddress((void**)&Qb, g_Q);
    cudaGetSymbolAddress((void**)&Kb, g_K);
    cudaGetSymbolAddress((void**)&Vb, g_V);
    cudaGetSymbolAddress((void**)&Ob, g_O);

    cudaFuncSetAttribute(flash_kernel,
                         cudaFuncAttributeMaxDynamicSharedMemorySize,
                         FLASH_SMEM);

    dim3 gblk(256);
    dim3 ggrd(C_ / GBN, M_ / GBM);   // (8, 32)

    // Q = x_q @ Wq + bq
    gemm_bias_kernel<<<ggrd, gblk>>>(x_q, Wq, bq, Qb, M_, C_, C_, 1, 0);
    // K = x_r @ Wk + bk
    gemm_bias_kernel<<<ggrd, gblk>>>(x_r, Wk, bk, Kb, M_, C_, C_, 1, 0);
    // V = sum_n (y_n @ Wv_n + bv_n)   -- single fused kernel over n
    gemm_bias_kernel<<<ggrd, gblk>>>(y, Wv, bv, Vb, M_, C_, C_, NI_,
                                     (size_t)M_ * C_);

    // Flash attention
    dim3 fgrd(B_ * H_, T_ / FBR);    // (32, 32)
    flash_kernel<<<fgrd, 256, FLASH_SMEM>>>(Qb, Kb, Vb, mask, dist, Ob);

    // out = O @ Wp + bp
    gemm_bias_kernel<<<ggrd, gblk>>>(Ob, Wp, bp, out, M_, C_, C_, 1, 0);
}

// round 5
// speedup vs baseline: 1.3803x; 1.3803x over previous
#include <cuda_runtime.h>
#include <cuda_bf16.h>
#include <cstdint>

// Problem shape (fixed by dataset)
#define B_  2
#define T_  2048
#define C_  1024
#define H_  16
#define HD_ 64
#define NI_ 3
#define M_  (B_ * T_)
#define NEG_ (-1e9f)

typedef __nv_bfloat16 bf16;

// -------- scratch (device globals; no allocation allowed) --------
__device__ float g_Q[(size_t)M_ * C_];
__device__ float g_K[(size_t)M_ * C_];
__device__ float g_V[(size_t)M_ * C_];
__device__ bf16 g_xqh[(size_t)M_ * C_],       g_xql[(size_t)M_ * C_];
__device__ bf16 g_xrh[(size_t)M_ * C_],       g_xrl[(size_t)M_ * C_];
__device__ bf16 g_yh [(size_t)NI_ * M_ * C_], g_yl [(size_t)NI_ * M_ * C_];
__device__ bf16 g_Oh [(size_t)M_ * C_],       g_Ol [(size_t)M_ * C_];
__device__ bf16 g_Wqh[(size_t)C_ * C_],       g_Wql[(size_t)C_ * C_];
__device__ bf16 g_Wkh[(size_t)C_ * C_],       g_Wkl[(size_t)C_ * C_];
__device__ bf16 g_Wvh[(size_t)NI_ * C_ * C_], g_Wvl[(size_t)NI_ * C_ * C_];
__device__ bf16 g_Wph[(size_t)C_ * C_],       g_Wpl[(size_t)C_ * C_];

// ============================================================================
// helpers
// ============================================================================
__device__ __forceinline__ uint32_t smem_u32(const void* p) {
    uint32_t a;
    asm("{ .reg .u64 t; cvta.to.shared.u64 t, %1; cvt.u32.u64 %0, t; }"
        : "=r"(a) : "l"(p));
    return a;
}
__device__ __forceinline__ uint32_t pack_bf16(float a, float b) {
    uint32_t ua = __bfloat16_as_ushort(__float2bfloat16_rn(a));
    uint32_t ub = __bfloat16_as_ushort(__float2bfloat16_rn(b));
    return (ub << 16) | ua;
}

#define CP_ASYNC16(dst, src) \
    asm volatile("cp.async.cg.shared.global [%0], [%1], 16;" :: "r"(dst), "l"(src))
#define CP_COMMIT() asm volatile("cp.async.commit_group;" ::: "memory")
#define CP_WAIT(n)  asm volatile("cp.async.wait_group %0;" :: "n"(n) : "memory")

#define LDSM_X4(r0, r1, r2, r3, addr) \
    asm volatile("ldmatrix.sync.aligned.m8n8.x4.shared.b16 {%0,%1,%2,%3}, [%4];" \
                 : "=r"(r0), "=r"(r1), "=r"(r2), "=r"(r3) : "r"(addr))
#define LDSM_X2T(r0, r1, addr) \
    asm volatile("ldmatrix.sync.aligned.m8n8.x2.trans.shared.b16 {%0,%1}, [%2];" \
                 : "=r"(r0), "=r"(r1) : "r"(addr))

#define MMA16816(d, a, b) \
    asm volatile("mma.sync.aligned.m16n8k16.row.col.f32.bf16.bf16.f32 " \
                 "{%0,%1,%2,%3}, {%4,%5,%6,%7}, {%8,%9}, {%0,%1,%2,%3};" \
                 : "+f"((d)[0]), "+f"((d)[1]), "+f"((d)[2]), "+f"((d)[3]) \
                 : "r"((a)[0]), "r"((a)[1]), "r"((a)[2]), "r"((a)[3]), \
                   "r"((b)[0]), "r"((b)[1]))

// ============================================================================
// split kernel: fp32 -> bf16 hi + bf16 lo (residual)
// ============================================================================
__global__ __launch_bounds__(256) void split_kernel(
    const float4* __restrict__ in, uint2* __restrict__ hi,
    uint2* __restrict__ lo, int n4)
{
    int i = blockIdx.x * 256 + threadIdx.x;
    if (i >= n4) return;
    float4 f = in[i];
    bf16 h0 = __float2bfloat16_rn(f.x);
    bf16 h1 = __float2bfloat16_rn(f.y);
    bf16 h2 = __float2bfloat16_rn(f.z);
    bf16 h3 = __float2bfloat16_rn(f.w);
    float l0 = f.x - __bfloat162float(h0);
    float l1 = f.y - __bfloat162float(h1);
    float l2 = f.z - __bfloat162float(h2);
    float l3 = f.w - __bfloat162float(h3);
    uint32_t hh0 = ((uint32_t)__bfloat16_as_ushort(h1) << 16) | __bfloat16_as_ushort(h0);
    uint32_t hh1 = ((uint32_t)__bfloat16_as_ushort(h3) << 16) | __bfloat16_as_ushort(h2);
    hi[i] = make_uint2(hh0, hh1);
    lo[i] = make_uint2(pack_bf16(l0, l1), pack_bf16(l2, l3));
}

// ============================================================================
// bf16 split GEMM via mma.sync.m16n8k16:
//   C = sum_n A_n[M,K] @ W_n[K,N] + sum_n bias_n[N]
// computed as Ah*Wh + Ah*Wl + Al*Wh in fp32 accum.
// CTA tile 128x128, K-chunk 64, 8 warps (2m x 4n), cp.async double buffer.
// A smem [128 m][64 k] stride 72 elems; W smem [64 k][128 n] stride 136 elems.
// ============================================================================
#define ASTR 72
#define WSTR 136
#define BKC  64
#define A_BYTES (128 * ASTR * 2)            // 18432
#define W_BYTES (64 * WSTR * 2)             // 17408
#define BUF_BYTES (2 * A_BYTES + 2 * W_BYTES)  // 71680
#define SMB_BUF 1024
#define GEMM_SMEM (SMB_BUF + 2 * BUF_BYTES)    // 144384

__device__ __forceinline__ void load_chunk(
    uint32_t sbuf, const bf16* __restrict__ Ah, const bf16* __restrict__ Al,
    const bf16* __restrict__ Wh, const bf16* __restrict__ Wl,
    int bm, int bn, int k0, int tid)
{
    // A: 128 rows x 64 k : 8 x 16B per row
    #pragma unroll
    for (int v = 0; v < 4; v++) {
        int idx = tid + v * 256;
        int r = idx >> 3, c = idx & 7;
        size_t go = (size_t)(bm + r) * C_ + k0 + c * 8;
        uint32_t so = sbuf + r * (ASTR * 2) + c * 16;
        CP_ASYNC16(so, Ah + go);
        CP_ASYNC16(so + A_BYTES, Al + go);
    }
    // W: 64 rows x 128 n : 16 x 16B per row
    #pragma unroll
    for (int v = 0; v < 4; v++) {
        int idx = tid + v * 256;
        int r = idx >> 4, c = idx & 15;
        size_t go = (size_t)(k0 + r) * C_ + bn + c * 8;
        uint32_t so = sbuf + 2 * A_BYTES + r * (WSTR * 2) + c * 16;
        CP_ASYNC16(so, Wh + go);
        CP_ASYNC16(so + W_BYTES, Wl + go);
    }
}

__device__ __forceinline__ void compute_chunk(
    uint32_t sbuf, int wm, int wn, int lane, float acc[4][4][4])
{
    const uint32_t smAh = sbuf;
    const uint32_t smAl = sbuf + A_BYTES;
    const uint32_t smWh = sbuf + 2 * A_BYTES;
    const uint32_t smWl = sbuf + 2 * A_BYTES + W_BYTES;
    const int m0 = wm * 64, n0 = wn * 32;
    const int ar = lane & 15;
    const int ac = (lane >> 4) << 3;

    #pragma unroll
    for (int ks = 0; ks < 4; ks++) {
        const int kk = ks * 16;
        uint32_t ah[4][4], al[4][4], bh[4][2], bl[4][2];
        #pragma unroll
        for (int mi = 0; mi < 4; mi++) {
            uint32_t off = ((m0 + mi * 16 + ar) * ASTR + kk + ac) * 2;
            LDSM_X4(ah[mi][0], ah[mi][1], ah[mi][2], ah[mi][3], smAh + off);
            LDSM_X4(al[mi][0], al[mi][1], al[mi][2], al[mi][3], smAl + off);
        }
        #pragma unroll
        for (int ni = 0; ni < 4; ni++) {
            uint32_t off = ((kk + ar) * WSTR + n0 + ni * 8) * 2;
            LDSM_X2T(bh[ni][0], bh[ni][1], smWh + off);
            LDSM_X2T(bl[ni][0], bl[ni][1], smWl + off);
        }
        #pragma unroll
        for (int mi = 0; mi < 4; mi++)
            #pragma unroll
            for (int ni = 0; ni < 4; ni++) {
                MMA16816(acc[mi][ni], ah[mi], bh[ni]);
                MMA16816(acc[mi][ni], ah[mi], bl[ni]);
                MMA16816(acc[mi][ni], al[mi], bh[ni]);
            }
    }
}

__global__ __launch_bounds__(256) void gemm_mma_kernel(
    const bf16* __restrict__ Ah, const bf16* __restrict__ Al,
    const bf16* __restrict__ Wh, const bf16* __restrict__ Wl,
    const float* __restrict__ bias, float* __restrict__ C,
    int nmat, size_t strideA, size_t strideW)
{
    extern __shared__ char smc[];
    const uint32_t smb = smem_u32(smc);
    float* s_bias = (float*)smc;

    const int tid = threadIdx.x;
    const int lane = tid & 31;
    const int wid = tid >> 5;
    const int wm = wid & 1;
    const int wn = wid >> 1;
    const int bm = blockIdx.y * 128;
    const int bn = blockIdx.x * 128;

    if (tid < 128) {
        float bs = 0.f;
        for (int n = 0; n < nmat; n++) bs += bias[(size_t)n * C_ + bn + tid];
        s_bias[tid] = bs;
    }

    float acc[4][4][4];
    #pragma unroll
    for (int mi = 0; mi < 4; mi++)
        #pragma unroll
        for (int ni = 0; ni < 4; ni++)
            #pragma unroll
            for (int r = 0; r < 4; r++) acc[mi][ni][r] = 0.f;

    const int NC = nmat * (C_ / BKC);   // chunks

    // prologue
    load_chunk(smb + SMB_BUF,
               Ah + (size_t)0 * strideA, Al, Wh, Wl, bm, bn, 0, tid);
    CP_COMMIT();

    for (int c = 0; c < NC; c++) {
        if (c + 1 < NC) {
            int nm = (c + 1) >> 4;
            int k0 = ((c + 1) & 15) * BKC;
            load_chunk(smb + SMB_BUF + ((c + 1) & 1) * BUF_BYTES,
                       Ah + (size_t)nm * strideA, Al + (size_t)nm * strideA,
                       Wh + (size_t)nm * strideW, Wl + (size_t)nm * strideW,
                       bm, bn, k0, tid);
            CP_COMMIT();
            CP_WAIT(1);
        } else {
            CP_WAIT(0);
        }
        __syncthreads();
        compute_chunk(smb + SMB_BUF + (c & 1) * BUF_BYTES, wm, wn, lane, acc);
        __syncthreads();
    }

    // epilogue
    const int r0 = bm + wm * 64 + (lane >> 2);
    const int c0rel = wn * 32 + 2 * (lane & 3);
    #pragma unroll
    for (int mi = 0; mi < 4; mi++) {
        #pragma unroll
        for (int ni = 0; ni < 4; ni++) {
            int crel = c0rel + ni * 8;
            float b0 = s_bias[crel], b1 = s_bias[crel + 1];
            int row = r0 + mi * 16;
            float2 v0 = make_float2(acc[mi][ni][0] + b0, acc[mi][ni][1] + b1);
            float2 v1 = make_float2(acc[mi][ni][2] + b0, acc[mi][ni][3] + b1);
            *(float2*)&C[(size_t)row * C_ + bn + crel] = v0;
            *(float2*)&C[(size_t)(row + 8) * C_ + bn + crel] = v1;
        }
    }
}

// ============================================================================
// Flash attention with post-softmax distance modulation (fp32).
// Writes O as bf16 hi/lo for the out-projection mma GEMM.
// ============================================================================
#define FBR 64
#define FBC 64
#define QSTRIDE 68
#define SSTRIDE 65
#define FLASH_SMEM ((3 * 64 * QSTRIDE + 64 * SSTRIDE + 3 * 64) * 4)

__global__ __launch_bounds__(256) void flash_kernel(
    const float* __restrict__ Q, const float* __restrict__ Kg,
    const float* __restrict__ Vg, const int* __restrict__ mask,
    const float* __restrict__ dist, bf16* __restrict__ Ohi,
    bf16* __restrict__ Olo)
{
    extern __shared__ float sm[];
    float* Qt   = sm;
    float* Kt   = Qt + 64 * QSTRIDE;
    float* Vs   = Kt + 64 * QSTRIDE;
    float* Ssm  = Vs + 64 * QSTRIDE;
    float* mrow = Ssm + 64 * SSTRIDE;
    float* lrow = mrow + 64;
    float* frow = lrow + 64;

    const int bh  = blockIdx.x;
    const int b   = bh >> 4;
    const int h   = bh & 15;
    const int t10 = blockIdx.y * FBR;
    const int tid = threadIdx.x;
    const int tx  = tid & 15;
    const int ty  = tid >> 4;

    {
        int i  = tid >> 2;
        int d0 = (tid & 3) << 4;
        const float* qp = &Q[((size_t)(b * T_ + t10 + i)) * C_ + h * HD_ + d0];
        #pragma unroll
        for (int v = 0; v < 4; v++) {
            float4 q4 = *(const float4*)(qp + v * 4);
            Qt[(d0 + v * 4 + 0) * QSTRIDE + i] = q4.x;
            Qt[(d0 + v * 4 + 1) * QSTRIDE + i] = q4.y;
            Qt[(d0 + v * 4 + 2) * QSTRIDE + i] = q4.z;
            Qt[(d0 + v * 4 + 3) * QSTRIDE + i] = q4.w;
        }
    }
    if (tid < 64) { mrow[tid] = -3.0e38f; lrow[tid] = 0.f; }

    float o[4][4];
    #pragma unroll
    for (int i = 0; i < 4; i++)
        #pragma unroll
        for (int j = 0; j < 4; j++) o[i][j] = 0.f;

    __syncthreads();

    for (int s0 = 0; s0 < T_; s0 += FBC) {
        {
            int j  = tid >> 2;
            int d0 = (tid & 3) << 4;
            const float* kp = &Kg[((size_t)(b * T_ + s0 + j)) * C_ + h * HD_ + d0];
            #pragma unroll
            for (int v = 0; v < 4; v++) {
                float4 k4 = *(const float4*)(kp + v * 4);
                Kt[(d0 + v * 4 + 0) * QSTRIDE + j] = k4.x;
                Kt[(d0 + v * 4 + 1) * QSTRIDE + j] = k4.y;
                Kt[(d0 + v * 4 + 2) * QSTRIDE + j] = k4.z;
                Kt[(d0 + v * 4 + 3) * QSTRIDE + j] = k4.w;
            }
            const float* vp = &Vg[((size_t)(b * T_ + s0 + j)) * C_ + h * HD_ + d0];
            #pragma unroll
            for (int v = 0; v < 4; v++)
                *(float4*)&Vs[j * QSTRIDE + d0 + v * 4] =
                    *(const float4*)(vp + v * 4);
        }
        __syncthreads();

        float sacc[4][4];
        #pragma unroll
        for (int i = 0; i < 4; i++)
            #pragma unroll
            for (int j = 0; j < 4; j++) sacc[i][j] = 0.f;

        #pragma unroll 8
        for (int d = 0; d < HD_; d++) {
            float4 qv = *(float4*)&Qt[d * QSTRIDE + ty * 4];
            float4 kv = *(float4*)&Kt[d * QSTRIDE + tx * 4];
            float qa[4] = {qv.x, qv.y, qv.z, qv.w};
            float ka[4] = {kv.x, kv.y, kv.z, kv.w};
            #pragma unroll
            for (int i = 0; i < 4; i++)
                #pragma unroll
                for (int j = 0; j < 4; j++)
                    sacc[i][j] += qa[i] * ka[j];
        }
        #pragma unroll
        for (int i = 0; i < 4; i++)
            #pragma unroll
            for (int j = 0; j < 4; j++)
                Ssm[(ty * 4 + i) * SSTRIDE + tx * 4 + j] = sacc[i][j] * 0.125f;
        __syncthreads();

        #pragma unroll
        for (int e = tid; e < FBR * FBC; e += 256) {
            int r = e >> 6, s = e & 63;
            int mk = mask[((size_t)b * T_ + t10 + r) * T_ + s0 + s];
            if (mk == 0) Ssm[r * SSTRIDE + s] = NEG_;
        }
        __syncthreads();

        if (tid < 64) {
            int r = tid;
            float mt = -3.0e38f;
            #pragma unroll 8
            for (int s = 0; s < FBC; s++)
                mt = fmaxf(mt, Ssm[r * SSTRIDE + s]);
            float m_old = mrow[r];
            float m_new = fmaxf(m_old, mt);
            float fr = __expf(m_old - m_new);
            float sum = 0.f;
            #pragma unroll 8
            for (int s = 0; s < FBC; s++) {
                float e = __expf(Ssm[r * SSTRIDE + s] - m_new);
                Ssm[r * SSTRIDE + s] = e;
                sum += e;
            }
            lrow[r] = lrow[r] * fr + sum;
            mrow[r] = m_new;
            frow[r] = fr;
        }
        __syncthreads();

        #pragma unroll
        for (int e = tid; e < FBR * FBC; e += 256) {
            int r = e >> 6, s = e & 63;
            float d = dist[((size_t)b * T_ + t10 + r) * T_ + s0 + s];
            Ssm[r * SSTRIDE + s] *= __expf(-4.0f * d * d);
        }
        __syncthreads();

        #pragma unroll
        for (int i = 0; i < 4; i++) {
            float fr = frow[ty * 4 + i];
            #pragma unroll
            for (int j = 0; j < 4; j++) o[i][j] *= fr;
        }
        #pragma unroll 4
        for (int s = 0; s < FBC; s++) {
            float4 vv = *(float4*)&Vs[s * QSTRIDE + tx * 4];
            float va[4] = {vv.x, vv.y, vv.z, vv.w};
            float p0 = Ssm[(ty * 4 + 0) * SSTRIDE + s];
            float p1 = Ssm[(ty * 4 + 1) * SSTRIDE + s];
            float p2 = Ssm[(ty * 4 + 2) * SSTRIDE + s];
            float p3 = Ssm[(ty * 4 + 3) * SSTRIDE + s];
            #pragma unroll
            for (int j = 0; j < 4; j++) {
                o[0][j] += p0 * va[j];
                o[1][j] += p1 * va[j];
                o[2][j] += p2 * va[j];
                o[3][j] += p3 * va[j];
            }
        }
        __syncthreads();
    }

    #pragma unroll
    for (int i = 0; i < 4; i++) {
        float inv = 1.0f / lrow[ty * 4 + i];
        float v[4];
        #pragma unroll
        for (int j = 0; j < 4; j++) v[j] = o[i][j] * inv;
        bf16 h0 = __float2bfloat16_rn(v[0]);
        bf16 h1 = __float2bfloat16_rn(v[1]);
        bf16 h2 = __float2bfloat16_rn(v[2]);
        bf16 h3 = __float2bfloat16_rn(v[3]);
        uint32_t hh0 = ((uint32_t)__bfloat16_as_ushort(h1) << 16) | __bfloat16_as_ushort(h0);
        uint32_t hh1 = ((uint32_t)__bfloat16_as_ushort(h3) << 16) | __bfloat16_as_ushort(h2);
        uint32_t ll0 = pack_bf16(v[0] - __bfloat162float(h0), v[1] - __bfloat162float(h1));
        uint32_t ll1 = pack_bf16(v[2] - __bfloat162float(h2), v[3] - __bfloat162float(h3));
        size_t idx = ((size_t)(b * T_ + t10 + ty * 4 + i)) * C_ + h * HD_ + tx * 4;
        *(uint2*)&Ohi[idx] = make_uint2(hh0, hh1);
        *(uint2*)&Olo[idx] = make_uint2(ll0, ll1);
    }
}

// ============================================================================
// Launch
// ============================================================================
extern "C" void kernel_launch(void* const* d_in, const int* in_sizes, int n_in,
                              void* d_out, int out_size)
{
    const float* x_q  = (const float*)d_in[0];
    const float* x_r  = (const float*)d_in[1];
    const float* y    = (const float*)d_in[2];
    const int*   mask = (const int*)  d_in[3];
    const float* dist = (const float*)d_in[4];
    const float* Wq   = (const float*)d_in[5];
    const float* bq   = (const float*)d_in[6];
    const float* Wk   = (const float*)d_in[7];
    const float* bk   = (const float*)d_in[8];
    const float* Wv   = (const float*)d_in[9];
    const float* bv   = (const float*)d_in[10];
    const float* Wp   = (const float*)d_in[11];
    const float* bp   = (const float*)d_in[12];
    float* out = (float*)d_out;

    float *Qb, *Kb, *Vb;
    bf16 *xqh, *xql, *xrh, *xrl, *yh, *yl, *Oh, *Ol;
    bf16 *wqh, *wql, *wkh, *wkl, *wvh, *wvl, *wph, *wpl;
    cudaGetSymbolAddress((void**)&Qb,  g_Q);
    cudaGetSymbolAddress((void**)&Kb,  g_K);
    cudaGetSymbolAddress((void**)&Vb,  g_V);
    cudaGetSymbolAddress((void**)&xqh, g_xqh);
    cudaGetSymbolAddress((void**)&xql, g_xql);
    cudaGetSymbolAddress((void**)&xrh, g_xrh);
    cudaGetSymbolAddress((void**)&xrl, g_xrl);
    cudaGetSymbolAddress((void**)&yh,  g_yh);
    cudaGetSymbolAddress((void**)&yl,  g_yl);
    cudaGetSymbolAddress((void**)&Oh,  g_Oh);
    cudaGetSymbolAddress((void**)&Ol,  g_Ol);
    cudaGetSymbolAddress((void**)&wqh, g_Wqh);
    cudaGetSymbolAddress((void**)&wql, g_Wql);
    cudaGetSymbolAddress((void**)&wkh, g_Wkh);
    cudaGetSymbolAddress((void**)&wkl, g_Wkl);
    cudaGetSymbolAddress((void**)&wvh, g_Wvh);
    cudaGetSymbolAddress((void**)&wvl, g_Wvl);
    cudaGetSymbolAddress((void**)&wph, g_Wph);
    cudaGetSymbolAddress((void**)&wpl, g_Wpl);

    cudaFuncSetAttribute(gemm_mma_kernel,
                         cudaFuncAttributeMaxDynamicSharedMemorySize, GEMM_SMEM);
    cudaFuncSetAttribute(flash_kernel,
                         cudaFuncAttributeMaxDynamicSharedMemorySize, FLASH_SMEM);

    // ---- split fp32 -> bf16 hi/lo ----
    const int MC4  = M_ * C_ / 4;           // 1M
    const int CC4  = C_ * C_ / 4;           // 256K
    split_kernel<<<MC4 / 256, 256>>>((const float4*)x_q, (uint2*)xqh, (uint2*)xql, MC4);
    split_kernel<<<MC4 / 256, 256>>>((const float4*)x_r, (uint2*)xrh, (uint2*)xrl, MC4);
    split_kernel<<<NI_ * MC4 / 256, 256>>>((const float4*)y, (uint2*)yh, (uint2*)yl, NI_ * MC4);
    split_kernel<<<CC4 / 256, 256>>>((const float4*)Wq, (uint2*)wqh, (uint2*)wql, CC4);
    split_kernel<<<CC4 / 256, 256>>>((const float4*)Wk, (uint2*)wkh, (uint2*)wkl, CC4);
    split_kernel<<<NI_ * CC4 / 256, 256>>>((const float4*)Wv, (uint2*)wvh, (uint2*)wvl, NI_ * CC4);
    split_kernel<<<CC4 / 256, 256>>>((const float4*)Wp, (uint2*)wph, (uint2*)wpl, CC4);

    dim3 gblk(256);
    dim3 ggrd(C_ / 128, M_ / 128);   // (8, 32)

    gemm_mma_kernel<<<ggrd, gblk, GEMM_SMEM>>>(xqh, xql, wqh, wql, bq, Qb, 1, 0, 0);
    gemm_mma_kernel<<<ggrd, gblk, GEMM_SMEM>>>(xrh, xrl, wkh, wkl, bk, Kb, 1, 0, 0);
    gemm_mma_kernel<<<ggrd, gblk, GEMM_SMEM>>>(yh, yl, wvh, wvl, bv, Vb, NI_,
                                               (size_t)M_ * C_, (size_t)C_ * C_);

    dim3 fgrd(B_ * H_, T_ / FBR);    // (32, 32)
    flash_kernel<<<fgrd, 256, FLASH_SMEM>>>(Qb, Kb, Vb, mask, dist, Oh, Ol);

    gemm_mma_kernel<<<ggrd, gblk, GEMM_SMEM>>>(Oh, Ol, wph, wpl, bp, out, 1, 0, 0);
}

// round 7
// speedup vs baseline: 1.9148x; 1.3872x over previous
#include <cuda_runtime.h>
#include <cuda_bf16.h>
#include <cstdint>

// Problem shape (fixed by dataset)
#define B_  2
#define T_  2048
#define C_  1024
#define H_  16
#define HD_ 64
#define NI_ 3
#define M_  (B_ * T_)
#define NEG_ (-1e9f)

typedef __nv_bfloat16 bf16;

// -------- scratch (device globals; no allocation allowed) --------
__device__ bf16 g_Qh[(size_t)M_ * C_],       g_Ql[(size_t)M_ * C_];
__device__ bf16 g_Kh[(size_t)M_ * C_],       g_Kl[(size_t)M_ * C_];
__device__ bf16 g_Vh[(size_t)M_ * C_],       g_Vl[(size_t)M_ * C_];
__device__ bf16 g_xqh[(size_t)M_ * C_],      g_xql[(size_t)M_ * C_];
__device__ bf16 g_xrh[(size_t)M_ * C_],      g_xrl[(size_t)M_ * C_];
__device__ bf16 g_yh [(size_t)NI_ * M_ * C_], g_yl [(size_t)NI_ * M_ * C_];
__device__ bf16 g_Oh [(size_t)M_ * C_],      g_Ol [(size_t)M_ * C_];
__device__ bf16 g_Wqh[(size_t)C_ * C_],      g_Wql[(size_t)C_ * C_];
__device__ bf16 g_Wkh[(size_t)C_ * C_],      g_Wkl[(size_t)C_ * C_];
__device__ bf16 g_Wvh[(size_t)NI_ * C_ * C_], g_Wvl[(size_t)NI_ * C_ * C_];
__device__ bf16 g_Wph[(size_t)C_ * C_],      g_Wpl[(size_t)C_ * C_];

// ============================================================================
// helpers
// ============================================================================
__device__ __forceinline__ uint32_t smem_u32(const void* p) {
    uint32_t a;
    asm("{ .reg .u64 t; cvta.to.shared.u64 t, %1; cvt.u32.u64 %0, t; }"
        : "=r"(a) : "l"(p));
    return a;
}
__device__ __forceinline__ uint32_t pack_bf16(float a, float b) {
    uint32_t ua = __bfloat16_as_ushort(__float2bfloat16_rn(a));
    uint32_t ub = __bfloat16_as_ushort(__float2bfloat16_rn(b));
    return (ub << 16) | ua;
}
__device__ __forceinline__ void split2(float a, float b, uint32_t& hi, uint32_t& lo) {
    bf16 h0 = __float2bfloat16_rn(a);
    bf16 h1 = __float2bfloat16_rn(b);
    hi = ((uint32_t)__bfloat16_as_ushort(h1) << 16) | __bfloat16_as_ushort(h0);
    lo = pack_bf16(a - __bfloat162float(h0), b - __bfloat162float(h1));
}

#define CP_ASYNC16(dst, src) \
    asm volatile("cp.async.cg.shared.global [%0], [%1], 16;" :: "r"(dst), "l"(src))
#define CP_COMMIT() asm volatile("cp.async.commit_group;" ::: "memory")
#define CP_WAIT(n)  asm volatile("cp.async.wait_group %0;" :: "n"(n) : "memory")

#define LDSM_X4(r0, r1, r2, r3, addr) \
    asm volatile("ldmatrix.sync.aligned.m8n8.x4.shared.b16 {%0,%1,%2,%3}, [%4];" \
                 : "=r"(r0), "=r"(r1), "=r"(r2), "=r"(r3) : "r"(addr))
#define LDSM_X2(r0, r1, addr) \
    asm volatile("ldmatrix.sync.aligned.m8n8.x2.shared.b16 {%0,%1}, [%2];" \
                 : "=r"(r0), "=r"(r1) : "r"(addr))
#define LDSM_X2T(r0, r1, addr) \
    asm volatile("ldmatrix.sync.aligned.m8n8.x2.trans.shared.b16 {%0,%1}, [%2];" \
                 : "=r"(r0), "=r"(r1) : "r"(addr))

#define MMA16816(d, a, b) \
    asm volatile("mma.sync.aligned.m16n8k16.row.col.f32.bf16.bf16.f32 " \
                 "{%0,%1,%2,%3}, {%4,%5,%6,%7}, {%8,%9}, {%0,%1,%2,%3};" \
                 : "+f"((d)[0]), "+f"((d)[1]), "+f"((d)[2]), "+f"((d)[3]) \
                 : "r"((a)[0]), "r"((a)[1]), "r"((a)[2]), "r"((a)[3]), \
                   "r"((b)[0]), "r"((b)[1]))

// ============================================================================
// split kernel: fp32 -> bf16 hi + bf16 lo (residual)
// ============================================================================
__global__ __launch_bounds__(256) void split_kernel(
    const float4* __restrict__ in, uint2* __restrict__ hi,
    uint2* __restrict__ lo, int n4)
{
    int i = blockIdx.x * 256 + threadIdx.x;
    if (i >= n4) return;
    float4 f = in[i];
    uint32_t h0, l0, h1, l1;
    split2(f.x, f.y, h0, l0);
    split2(f.z, f.w, h1, l1);
    hi[i] = make_uint2(h0, h1);
    lo[i] = make_uint2(l0, l1);
}

// ============================================================================
// bf16 split GEMM via mma.sync.m16n8k16:
//   C = sum_n A_n[M,K] @ W_n[K,N] + sum_n bias_n[N]
// outmode 0: fp32 to C.  outmode 1: bf16 hi/lo to Chi/Clo.
// ============================================================================
#define ASTR 72
#define WSTR 136
#define BKC  64
#define A_BYTES (128 * ASTR * 2)
#define W_BYTES (64 * WSTR * 2)
#define BUF_BYTES (2 * A_BYTES + 2 * W_BYTES)
#define SMB_BUF 1024
#define GEMM_SMEM (SMB_BUF + 2 * BUF_BYTES)

__device__ __forceinline__ void load_chunk(
    uint32_t sbuf, const bf16* __restrict__ Ah, const bf16* __restrict__ Al,
    const bf16* __restrict__ Wh, const bf16* __restrict__ Wl,
    int bm, int bn, int k0, int tid)
{
    #pragma unroll
    for (int v = 0; v < 4; v++) {
        int idx = tid + v * 256;
        int r = idx >> 3, c = idx & 7;
        size_t go = (size_t)(bm + r) * C_ + k0 + c * 8;
        uint32_t so = sbuf + r * (ASTR * 2) + c * 16;
        CP_ASYNC16(so, Ah + go);
        CP_ASYNC16(so + A_BYTES, Al + go);
    }
    #pragma unroll
    for (int v = 0; v < 4; v++) {
        int idx = tid + v * 256;
        int r = idx >> 4, c = idx & 15;
        size_t go = (size_t)(k0 + r) * C_ + bn + c * 8;
        uint32_t so = sbuf + 2 * A_BYTES + r * (WSTR * 2) + c * 16;
        CP_ASYNC16(so, Wh + go);
        CP_ASYNC16(so + W_BYTES, Wl + go);
    }
}

__device__ __forceinline__ void compute_chunk(
    uint32_t sbuf, int wm, int wn, int lane, float acc[4][4][4])
{
    const uint32_t smAh = sbuf;
    const uint32_t smAl = sbuf + A_BYTES;
    const uint32_t smWh = sbuf + 2 * A_BYTES;
    const uint32_t smWl = sbuf + 2 * A_BYTES + W_BYTES;
    const int m0 = wm * 64, n0 = wn * 32;
    const int ar = lane & 15;
    const int ac = (lane >> 4) << 3;

    #pragma unroll
    for (int ks = 0; ks < 4; ks++) {
        const int kk = ks * 16;
        uint32_t ah[4][4], al[4][4], bh[4][2], bl[4][2];
        #pragma unroll
        for (int mi = 0; mi < 4; mi++) {
            uint32_t off = ((m0 + mi * 16 + ar) * ASTR + kk + ac) * 2;
            LDSM_X4(ah[mi][0], ah[mi][1], ah[mi][2], ah[mi][3], smAh + off);
            LDSM_X4(al[mi][0], al[mi][1], al[mi][2], al[mi][3], smAl + off);
        }
        #pragma unroll
        for (int ni = 0; ni < 4; ni++) {
            uint32_t off = ((kk + ar) * WSTR + n0 + ni * 8) * 2;
            LDSM_X2T(bh[ni][0], bh[ni][1], smWh + off);
            LDSM_X2T(bl[ni][0], bl[ni][1], smWl + off);
        }
        #pragma unroll
        for (int mi = 0; mi < 4; mi++)
            #pragma unroll
            for (int ni = 0; ni < 4; ni++) {
                MMA16816(acc[mi][ni], ah[mi], bh[ni]);
                MMA16816(acc[mi][ni], ah[mi], bl[ni]);
                MMA16816(acc[mi][ni], al[mi], bh[ni]);
            }
    }
}

__global__ __launch_bounds__(256) void gemm_mma_kernel(
    const bf16* __restrict__ Ah, const bf16* __restrict__ Al,
    const bf16* __restrict__ Wh, const bf16* __restrict__ Wl,
    const float* __restrict__ bias, float* __restrict__ C,
    bf16* __restrict__ Chi, bf16* __restrict__ Clo,
    int nmat, size_t strideA, size_t strideW, int outmode)
{
    extern __shared__ char smc[];
    const uint32_t smb = smem_u32(smc);
    float* s_bias = (float*)smc;

    const int tid = threadIdx.x;
    const int lane = tid & 31;
    const int wid = tid >> 5;
    const int wm = wid & 1;
    const int wn = wid >> 1;
    const int bm = blockIdx.y * 128;
    const int bn = blockIdx.x * 128;

    if (tid < 128) {
        float bs = 0.f;
        for (int n = 0; n < nmat; n++) bs += bias[(size_t)n * C_ + bn + tid];
        s_bias[tid] = bs;
    }

    float acc[4][4][4];
    #pragma unroll
    for (int mi = 0; mi < 4; mi++)
        #pragma unroll
        for (int ni = 0; ni < 4; ni++)
            #pragma unroll
            for (int r = 0; r < 4; r++) acc[mi][ni][r] = 0.f;

    const int NC = nmat * (C_ / BKC);

    load_chunk(smb + SMB_BUF, Ah, Al, Wh, Wl, bm, bn, 0, tid);
    CP_COMMIT();

    for (int c = 0; c < NC; c++) {
        if (c + 1 < NC) {
            int nm = (c + 1) >> 4;
            int k0 = ((c + 1) & 15) * BKC;
            load_chunk(smb + SMB_BUF + ((c + 1) & 1) * BUF_BYTES,
                       Ah + (size_t)nm * strideA, Al + (size_t)nm * strideA,
                       Wh + (size_t)nm * strideW, Wl + (size_t)nm * strideW,
                       bm, bn, k0, tid);
            CP_COMMIT();
            CP_WAIT(1);
        } else {
            CP_WAIT(0);
        }
        __syncthreads();
        compute_chunk(smb + SMB_BUF + (c & 1) * BUF_BYTES, wm, wn, lane, acc);
        __syncthreads();
    }

    const int r0 = bm + wm * 64 + (lane >> 2);
    const int c0rel = wn * 32 + 2 * (lane & 3);
    #pragma unroll
    for (int mi = 0; mi < 4; mi++) {
        #pragma unroll
        for (int ni = 0; ni < 4; ni++) {
            int crel = c0rel + ni * 8;
            float b0 = s_bias[crel], b1 = s_bias[crel + 1];
            int row = r0 + mi * 16;
            float a0 = acc[mi][ni][0] + b0, a1 = acc[mi][ni][1] + b1;
            float a2 = acc[mi][ni][2] + b0, a3 = acc[mi][ni][3] + b1;
            if (outmode == 0) {
                *(float2*)&C[(size_t)row * C_ + bn + crel] = make_float2(a0, a1);
                *(float2*)&C[(size_t)(row + 8) * C_ + bn + crel] = make_float2(a2, a3);
            } else {
                uint32_t h0, l0, h1, l1;
                split2(a0, a1, h0, l0);
                split2(a2, a3, h1, l1);
                *(uint32_t*)&Chi[(size_t)row * C_ + bn + crel] = h0;
                *(uint32_t*)&Clo[(size_t)row * C_ + bn + crel] = l0;
                *(uint32_t*)&Chi[(size_t)(row + 8) * C_ + bn + crel] = h1;
                *(uint32_t*)&Clo[(size_t)(row + 8) * C_ + bn + crel] = l1;
            }
        }
    }
}

// ============================================================================
// Flash attention on mma.sync (bf16 split QK^T, split P x split V).
// CTA: 128 q-rows, iterates kv in chunks of 64. 8 warps (16 q-rows each).
// Post-softmax dist modulation applied to numerator only.
// ============================================================================
#define FQ 128
#define FS 64
#define FSTR 72                 // bf16 row stride (elems) for Q/K/V/P tiles
#define SSTRf 66                // fp32 row stride for S
#define OFF_QH 0
#define OFF_QL 18432
#define OFF_BUF 36864           // 2 bufs x 36864 (KH,KL,VH,VL @ +0,+9216,+18432,+27648)
#define KV_BUF_BYTES 36864
#define OFF_S  110592
#define OFF_PH 144384
#define OFF_PL 162816
#define OFF_MR 181248
#define OFF_LR 181760
#define OFF_FR 182272
#define FLASH_SMEM 182784

__global__ __launch_bounds__(256) void flash_mma_kernel(
    const bf16* __restrict__ Qh, const bf16* __restrict__ Ql,
    const bf16* __restrict__ Kh, const bf16* __restrict__ Kl,
    const bf16* __restrict__ Vh, const bf16* __restrict__ Vl,
    const int* __restrict__ mask, const float* __restrict__ dist,
    bf16* __restrict__ Ohi, bf16* __restrict__ Olo)
{
    extern __shared__ char smc[];
    const uint32_t smb = smem_u32(smc);
    float* S    = (float*)(smc + OFF_S);
    float* mrow = (float*)(smc + OFF_MR);
    float* lrow = (float*)(smc + OFF_LR);
    float* frow = (float*)(smc + OFF_FR);

    const int bh  = blockIdx.x;          // 0..31
    const int b   = bh >> 4;
    const int h   = bh & 15;
    const int t10 = blockIdx.y * FQ;
    const int tid = threadIdx.x;
    const int lane = tid & 31;
    const int wid = tid >> 5;
    const int m0 = wid * 16;

    // ---- load Q tile (128 x 64, hi/lo) via cp.async ----
    #pragma unroll
    for (int v = 0; v < 4; v++) {
        int idx = tid + v * 256;         // 0..1023
        int r = idx >> 3, c = idx & 7;
        size_t go = (size_t)(b * T_ + t10 + r) * C_ + h * HD_ + c * 8;
        uint32_t so = smb + r * (FSTR * 2) + c * 16;
        CP_ASYNC16(so + OFF_QH, Qh + go);
        CP_ASYNC16(so + OFF_QL, Ql + go);
    }
    CP_COMMIT();

    // ---- preload kv chunk 0 ----
    {
        #pragma unroll
        for (int v = 0; v < 2; v++) {
            int idx = tid + v * 256;     // 0..511
            int r = idx >> 3, c = idx & 7;
            size_t go = (size_t)(b * T_ + r) * C_ + h * HD_ + c * 8;
            uint32_t so = smb + OFF_BUF + r * (FSTR * 2) + c * 16;
            CP_ASYNC16(so,         Kh + go);
            CP_ASYNC16(so + 9216,  Kl + go);
            CP_ASYNC16(so + 18432, Vh + go);
            CP_ASYNC16(so + 27648, Vl + go);
        }
        CP_COMMIT();
    }

    if (tid < FQ) { mrow[tid] = -3.0e38f; lrow[tid] = 0.f; }

    float oacc[8][4];
    #pragma unroll
    for (int ni = 0; ni < 8; ni++)
        #pragma unroll
        for (int r = 0; r < 4; r++) oacc[ni][r] = 0.f;

    const int NITER = T_ / FS;           // 32

    for (int it = 0; it < NITER; it++) {
        // prefetch next chunk
        if (it + 1 < NITER) {
            int s0n = (it + 1) * FS;
            uint32_t bb = smb + OFF_BUF + ((it + 1) & 1) * KV_BUF_BYTES;
            #pragma unroll
            for (int v = 0; v < 2; v++) {
                int idx = tid + v * 256;
                int r = idx >> 3, c = idx & 7;
                size_t go = (size_t)(b * T_ + s0n + r) * C_ + h * HD_ + c * 8;
                uint32_t so = bb + r * (FSTR * 2) + c * 16;
                CP_ASYNC16(so,         Kh + go);
                CP_ASYNC16(so + 9216,  Kl + go);
                CP_ASYNC16(so + 18432, Vh + go);
                CP_ASYNC16(so + 27648, Vl + go);
            }
            CP_COMMIT();
            CP_WAIT(1);
        } else {
            CP_WAIT(0);
        }
        __syncthreads();

        const int s0 = it * FS;
        const uint32_t bb = smb + OFF_BUF + (it & 1) * KV_BUF_BYTES;
        const uint32_t smKh = bb, smKl = bb + 9216;
        const uint32_t smVh = bb + 18432, smVl = bb + 27648;

        // ---- S = Q K^T (hi*hi + hi*lo + lo*hi) ----
        float sacc[8][4];
        #pragma unroll
        for (int ni = 0; ni < 8; ni++)
            #pragma unroll
            for (int r = 0; r < 4; r++) sacc[ni][r] = 0.f;

        #pragma unroll
        for (int ks = 0; ks < 4; ks++) {
            const int k0 = ks * 16;
            uint32_t qh[4], ql[4];
            uint32_t aoff = ((m0 + (lane & 15)) * FSTR + k0 + ((lane >> 4) << 3)) * 2;
            LDSM_X4(qh[0], qh[1], qh[2], qh[3], smb + OFF_QH + aoff);
            LDSM_X4(ql[0], ql[1], ql[2], ql[3], smb + OFF_QL + aoff);
            #pragma unroll
            for (int ni = 0; ni < 8; ni++) {
                uint32_t kbh[2], kbl[2];
                uint32_t boff = ((ni * 8 + (lane & 7)) * FSTR + k0 +
                                 ((lane >> 3) & 1) * 8) * 2;
                LDSM_X2(kbh[0], kbh[1], smKh + boff);
                LDSM_X2(kbl[0], kbl[1], smKl + boff);
                MMA16816(sacc[ni], qh, kbh);
                MMA16816(sacc[ni], qh, kbl);
                MMA16816(sacc[ni], ql, kbh);
            }
        }

        // write S (scaled) to smem
        {
            int r0 = m0 + (lane >> 2);
            int cq = (lane & 3) * 2;
            #pragma unroll
            for (int ni = 0; ni < 8; ni++) {
                int c = ni * 8 + cq;
                *(float2*)&S[r0 * SSTRf + c] =
                    make_float2(sacc[ni][0] * 0.125f, sacc[ni][1] * 0.125f);
                *(float2*)&S[(r0 + 8) * SSTRf + c] =
                    make_float2(sacc[ni][2] * 0.125f, sacc[ni][3] * 0.125f);
            }
        }
        __syncthreads();

        // ---- mask pass (coalesced pairs) ----
        #pragma unroll
        for (int p = 0; p < 16; p++) {
            int e = (tid + p * 256) * 2;          // element pair index
            int r = e >> 6, s = e & 63;
            int2 mk = *(const int2*)&mask[(size_t)(b * T_ + t10 + r) * T_ + s0 + s];
            if (mk.x == 0) S[r * SSTRf + s] = NEG_;
            if (mk.y == 0) S[r * SSTRf + s + 1] = NEG_;
        }
        __syncthreads();

        // ---- row stats (128 threads, one row each) ----
        if (tid < FQ) {
            int r = tid;
            float* Sr = &S[r * SSTRf];
            float mt = -3.0e38f;
            #pragma unroll 8
            for (int s = 0; s < FS; s++) mt = fmaxf(mt, Sr[s]);
            float m_old = mrow[r];
            float m_new = fmaxf(m_old, mt);
            float fr = __expf(m_old - m_new);
            float sum = 0.f;
            #pragma unroll 8
            for (int s = 0; s < FS; s++) {
                float e = __expf(Sr[s] - m_new);
                Sr[s] = e;
                sum += e;
            }
            lrow[r] = lrow[r] * fr + sum;
            mrow[r] = m_new;
            frow[r] = fr;
        }
        __syncthreads();

        // ---- P = e * exp(-4 d^2), split to bf16 hi/lo (numerator-only) ----
        uint16_t* Ph = (uint16_t*)(smc + OFF_PH);
        uint16_t* Pl = (uint16_t*)(smc + OFF_PL);
        #pragma unroll
        for (int p = 0; p < 16; p++) {
            int e2 = (tid + p * 256) * 2;
            int r = e2 >> 6, s = e2 & 63;
            float2 d2 = *(const float2*)&dist[(size_t)(b * T_ + t10 + r) * T_ + s0 + s];
            float w0 = __expf(-4.0f * d2.x * d2.x);
            float w1 = __expf(-4.0f * d2.y * d2.y);
            float2 ee = *(float2*)&S[r * SSTRf + s];
            uint32_t ph, pl;
            split2(ee.x * w0, ee.y * w1, ph, pl);
            *(uint32_t*)&Ph[r * FSTR + s] = ph;
            *(uint32_t*)&Pl[r * FSTR + s] = pl;
        }
        __syncthreads();

        // ---- rescale O, then O += P @ V (Ph*Vh + Ph*Vl + Pl*Vh) ----
        {
            float f0 = frow[m0 + (lane >> 2)];
            float f1 = frow[m0 + 8 + (lane >> 2)];
            #pragma unroll
            for (int ni = 0; ni < 8; ni++) {
                oacc[ni][0] *= f0; oacc[ni][1] *= f0;
                oacc[ni][2] *= f1; oacc[ni][3] *= f1;
            }
        }
        #pragma unroll
        for (int ks = 0; ks < 4; ks++) {
            uint32_t pa[4], pb[4];
            uint32_t aoff = ((m0 + (lane & 15)) * FSTR + ks * 16 +
                             ((lane >> 4) << 3)) * 2;
            LDSM_X4(pa[0], pa[1], pa[2], pa[3], smb + OFF_PH + aoff);
            LDSM_X4(pb[0], pb[1], pb[2], pb[3], smb + OFF_PL + aoff);
            #pragma unroll
            for (int ni = 0; ni < 8; ni++) {
                uint32_t vbh[2], vbl[2];
                uint32_t boff = ((ks * 16 + (lane & 15)) * FSTR + ni * 8) * 2;
                LDSM_X2T(vbh[0], vbh[1], smVh + boff);
                LDSM_X2T(vbl[0], vbl[1], smVl + boff);
                MMA16816(oacc[ni], pa, vbh);
                MMA16816(oacc[ni], pa, vbl);
                MMA16816(oacc[ni], pb, vbh);
            }
        }
        __syncthreads();
    }

    // ---- epilogue: /l, write bf16 hi/lo ----
    {
        int r0 = m0 + (lane >> 2);
        int cq = (lane & 3) * 2;
        float inv0 = 1.0f / lrow[r0];
        float inv1 = 1.0f / lrow[r0 + 8];
        size_t row0 = (size_t)(b * T_ + t10 + r0) * C_ + h * HD_;
        size_t row1 = (size_t)(b * T_ + t10 + r0 + 8) * C_ + h * HD_;
        #pragma unroll
        for (int ni = 0; ni < 8; ni++) {
            int c = ni * 8 + cq;
            uint32_t h0, l0, h1, l1;
            split2(oacc[ni][0] * inv0, oacc[ni][1] * inv0, h0, l0);
            split2(oacc[ni][2] * inv1, oacc[ni][3] * inv1, h1, l1);
            *(uint32_t*)&Ohi[row0 + c] = h0;
            *(uint32_t*)&Olo[row0 + c] = l0;
            *(uint32_t*)&Ohi[row1 + c] = h1;
            *(uint32_t*)&Olo[row1 + c] = l1;
        }
    }
}

// ============================================================================
// Launch
// ============================================================================
extern "C" void kernel_launch(void* const* d_in, const int* in_sizes, int n_in,
                              void* d_out, int out_size)
{
    const float* x_q  = (const float*)d_in[0];
    const float* x_r  = (const float*)d_in[1];
    const float* y    = (const float*)d_in[2];
    const int*   mask = (const int*)  d_in[3];
    const float* dist = (const float*)d_in[4];
    const float* Wq   = (const float*)d_in[5];
    const float* bq   = (const float*)d_in[6];
    const float* Wk   = (const float*)d_in[7];
    const float* bk   = (const float*)d_in[8];
    const float* Wv   = (const float*)d_in[9];
    const float* bv   = (const float*)d_in[10];
    const float* Wp   = (const float*)d_in[11];
    const float* bp   = (const float*)d_in[12];
    float* out = (float*)d_out;

    bf16 *qh, *ql, *kh, *kl, *vh, *vl;
    bf16 *xqh, *xql, *xrh, *xrl, *yh, *yl, *Oh, *Ol;
    bf16 *wqh, *wql, *wkh, *wkl, *wvh, *wvl, *wph, *wpl;
    cudaGetSymbolAddress((void**)&qh,  g_Qh);
    cudaGetSymbolAddress((void**)&ql,  g_Ql);
    cudaGetSymbolAddress((void**)&kh,  g_Kh);
    cudaGetSymbolAddress((void**)&kl,  g_Kl);
    cudaGetSymbolAddress((void**)&vh,  g_Vh);
    cudaGetSymbolAddress((void**)&vl,  g_Vl);
    cudaGetSymbolAddress((void**)&xqh, g_xqh);
    cudaGetSymbolAddress((void**)&xql, g_xql);
    cudaGetSymbolAddress((void**)&xrh, g_xrh);
    cudaGetSymbolAddress((void**)&xrl, g_xrl);
    cudaGetSymbolAddress((void**)&yh,  g_yh);
    cudaGetSymbolAddress((void**)&yl,  g_yl);
    cudaGetSymbolAddress((void**)&Oh,  g_Oh);
    cudaGetSymbolAddress((void**)&Ol,  g_Ol);
    cudaGetSymbolAddress((void**)&wqh, g_Wqh);
    cudaGetSymbolAddress((void**)&wql, g_Wql);
    cudaGetSymbolAddress((void**)&wkh, g_Wkh);
    cudaGetSymbolAddress((void**)&wkl, g_Wkl);
    cudaGetSymbolAddress((void**)&wvh, g_Wvh);
    cudaGetSymbolAddress((void**)&wvl, g_Wvl);
    cudaGetSymbolAddress((void**)&wph, g_Wph);
    cudaGetSymbolAddress((void**)&wpl, g_Wpl);

    cudaFuncSetAttribute(gemm_mma_kernel,
                         cudaFuncAttributeMaxDynamicSharedMemorySize, GEMM_SMEM);
    cudaFuncSetAttribute(flash_mma_kernel,
                         cudaFuncAttributeMaxDynamicSharedMemorySize, FLASH_SMEM);

    // ---- split fp32 inputs -> bf16 hi/lo ----
    const int MC4 = M_ * C_ / 4;
    const int CC4 = C_ * C_ / 4;
    split_kernel<<<MC4 / 256, 256>>>((const float4*)x_q, (uint2*)xqh, (uint2*)xql, MC4);
    split_kernel<<<MC4 / 256, 256>>>((const float4*)x_r, (uint2*)xrh, (uint2*)xrl, MC4);
    split_kernel<<<NI_ * MC4 / 256, 256>>>((const float4*)y, (uint2*)yh, (uint2*)yl, NI_ * MC4);
    split_kernel<<<CC4 / 256, 256>>>((const float4*)Wq, (uint2*)wqh, (uint2*)wql, CC4);
    split_kernel<<<CC4 / 256, 256>>>((const float4*)Wk, (uint2*)wkh, (uint2*)wkl, CC4);
    split_kernel<<<NI_ * CC4 / 256, 256>>>((const float4*)Wv, (uint2*)wvh, (uint2*)wvl, NI_ * CC4);
    split_kernel<<<CC4 / 256, 256>>>((const float4*)Wp, (uint2*)wph, (uint2*)wpl, CC4);

    dim3 gblk(256);
    dim3 ggrd(C_ / 128, M_ / 128);

    // projections -> bf16 hi/lo outputs
    gemm_mma_kernel<<<ggrd, gblk, GEMM_SMEM>>>(xqh, xql, wqh, wql, bq,
                                               nullptr, qh, ql, 1, 0, 0, 1);
    gemm_mma_kernel<<<ggrd, gblk, GEMM_SMEM>>>(xrh, xrl, wkh, wkl, bk,
                                               nullptr, kh, kl, 1, 0, 0, 1);
    gemm_mma_kernel<<<ggrd, gblk, GEMM_SMEM>>>(yh, yl, wvh, wvl, bv,
                                               nullptr, vh, vl, NI_,
                                               (size_t)M_ * C_, (size_t)C_ * C_, 1);

    // flash attention
    dim3 fgrd(B_ * H_, T_ / FQ);         // (32, 16)
    flash_mma_kernel<<<fgrd, 256, FLASH_SMEM>>>(qh, ql, kh, kl, vh, vl,
                                                mask, dist, Oh, Ol);

    // out projection -> fp32
    gemm_mma_kernel<<<ggrd, gblk, GEMM_SMEM>>>(Oh, Ol, wph, wpl, bp,
                                               out, nullptr, nullptr, 1, 0, 0, 0);
}

// round 8
// speedup vs baseline: 2.3456x; 1.2250x over previous
#include <cuda_runtime.h>
#include <cuda_bf16.h>
#include <cstdint>

// Problem shape (fixed by dataset)
#define B_  2
#define T_  2048
#define C_  1024
#define H_  16
#define HD_ 64
#define NI_ 3
#define M_  (B_ * T_)
#define NEG_ (-1e9f)

typedef __nv_bfloat16 bf16;

// -------- scratch (device globals; no allocation allowed) --------
__device__ bf16 g_Qh[(size_t)M_ * C_],       g_Ql[(size_t)M_ * C_];
__device__ bf16 g_Kh[(size_t)M_ * C_],       g_Kl[(size_t)M_ * C_];
__device__ bf16 g_Vh[(size_t)M_ * C_],       g_Vl[(size_t)M_ * C_];
__device__ bf16 g_xqh[(size_t)M_ * C_],      g_xql[(size_t)M_ * C_];
__device__ bf16 g_xrh[(size_t)M_ * C_],      g_xrl[(size_t)M_ * C_];
__device__ bf16 g_yh [(size_t)NI_ * M_ * C_], g_yl [(size_t)NI_ * M_ * C_];
__device__ bf16 g_Oh [(size_t)M_ * C_],      g_Ol [(size_t)M_ * C_];
__device__ bf16 g_Wqh[(size_t)C_ * C_],      g_Wql[(size_t)C_ * C_];
__device__ bf16 g_Wkh[(size_t)C_ * C_],      g_Wkl[(size_t)C_ * C_];
__device__ bf16 g_Wvh[(size_t)NI_ * C_ * C_], g_Wvl[(size_t)NI_ * C_ * C_];
__device__ bf16 g_Wph[(size_t)C_ * C_],      g_Wpl[(size_t)C_ * C_];

// ============================================================================
// helpers
// ============================================================================
__device__ __forceinline__ uint32_t smem_u32(const void* p) {
    uint32_t a;
    asm("{ .reg .u64 t; cvta.to.shared.u64 t, %1; cvt.u32.u64 %0, t; }"
        : "=r"(a) : "l"(p));
    return a;
}
__device__ __forceinline__ uint32_t pack_bf16(float a, float b) {
    uint32_t ua = __bfloat16_as_ushort(__float2bfloat16_rn(a));
    uint32_t ub = __bfloat16_as_ushort(__float2bfloat16_rn(b));
    return (ub << 16) | ua;
}
__device__ __forceinline__ void split2(float a, float b, uint32_t& hi, uint32_t& lo) {
    bf16 h0 = __float2bfloat16_rn(a);
    bf16 h1 = __float2bfloat16_rn(b);
    hi = ((uint32_t)__bfloat16_as_ushort(h1) << 16) | __bfloat16_as_ushort(h0);
    lo = pack_bf16(a - __bfloat162float(h0), b - __bfloat162float(h1));
}

#define CP_ASYNC16(dst, src) \
    asm volatile("cp.async.cg.shared.global [%0], [%1], 16;" :: "r"(dst), "l"(src))
#define CP_COMMIT() asm volatile("cp.async.commit_group;" ::: "memory")
#define CP_WAIT(n)  asm volatile("cp.async.wait_group %0;" :: "n"(n) : "memory")

#define LDSM_X4(r0, r1, r2, r3, addr) \
    asm volatile("ldmatrix.sync.aligned.m8n8.x4.shared.b16 {%0,%1,%2,%3}, [%4];" \
                 : "=r"(r0), "=r"(r1), "=r"(r2), "=r"(r3) : "r"(addr))
#define LDSM_X2(r0, r1, addr) \
    asm volatile("ldmatrix.sync.aligned.m8n8.x2.shared.b16 {%0,%1}, [%2];" \
                 : "=r"(r0), "=r"(r1) : "r"(addr))
#define LDSM_X2T(r0, r1, addr) \
    asm volatile("ldmatrix.sync.aligned.m8n8.x2.trans.shared.b16 {%0,%1}, [%2];" \
                 : "=r"(r0), "=r"(r1) : "r"(addr))

#define MMA16816(d, a, b) \
    asm volatile("mma.sync.aligned.m16n8k16.row.col.f32.bf16.bf16.f32 " \
                 "{%0,%1,%2,%3}, {%4,%5,%6,%7}, {%8,%9}, {%0,%1,%2,%3};" \
                 : "+f"((d)[0]), "+f"((d)[1]), "+f"((d)[2]), "+f"((d)[3]) \
                 : "r"((a)[0]), "r"((a)[1]), "r"((a)[2]), "r"((a)[3]), \
                   "r"((b)[0]), "r"((b)[1]))

// ============================================================================
// split kernel: fp32 -> bf16 hi + bf16 lo (residual)
// ============================================================================
__global__ __launch_bounds__(256) void split_kernel(
    const float4* __restrict__ in, uint2* __restrict__ hi,
    uint2* __restrict__ lo, int n4)
{
    int i = blockIdx.x * 256 + threadIdx.x;
    if (i >= n4) return;
    float4 f = in[i];
    uint32_t h0, l0, h1, l1;
    split2(f.x, f.y, h0, l0);
    split2(f.z, f.w, h1, l1);
    hi[i] = make_uint2(h0, h1);
    lo[i] = make_uint2(l0, l1);
}

// ============================================================================
// bf16 split GEMM via mma.sync.m16n8k16 (unchanged from R7)
// ============================================================================
#define ASTR 72
#define WSTR 136
#define BKC  64
#define A_BYTES (128 * ASTR * 2)
#define W_BYTES (64 * WSTR * 2)
#define BUF_BYTES (2 * A_BYTES + 2 * W_BYTES)
#define SMB_BUF 1024
#define GEMM_SMEM (SMB_BUF + 2 * BUF_BYTES)

__device__ __forceinline__ void load_chunk(
    uint32_t sbuf, const bf16* __restrict__ Ah, const bf16* __restrict__ Al,
    const bf16* __restrict__ Wh, const bf16* __restrict__ Wl,
    int bm, int bn, int k0, int tid)
{
    #pragma unroll
    for (int v = 0; v < 4; v++) {
        int idx = tid + v * 256;
        int r = idx >> 3, c = idx & 7;
        size_t go = (size_t)(bm + r) * C_ + k0 + c * 8;
        uint32_t so = sbuf + r * (ASTR * 2) + c * 16;
        CP_ASYNC16(so, Ah + go);
        CP_ASYNC16(so + A_BYTES, Al + go);
    }
    #pragma unroll
    for (int v = 0; v < 4; v++) {
        int idx = tid + v * 256;
        int r = idx >> 4, c = idx & 15;
        size_t go = (size_t)(k0 + r) * C_ + bn + c * 8;
        uint32_t so = sbuf + 2 * A_BYTES + r * (WSTR * 2) + c * 16;
        CP_ASYNC16(so, Wh + go);
        CP_ASYNC16(so + W_BYTES, Wl + go);
    }
}

__device__ __forceinline__ void compute_chunk(
    uint32_t sbuf, int wm, int wn, int lane, float acc[4][4][4])
{
    const uint32_t smAh = sbuf;
    const uint32_t smAl = sbuf + A_BYTES;
    const uint32_t smWh = sbuf + 2 * A_BYTES;
    const uint32_t smWl = sbuf + 2 * A_BYTES + W_BYTES;
    const int m0 = wm * 64, n0 = wn * 32;
    const int ar = lane & 15;
    const int ac = (lane >> 4) << 3;

    #pragma unroll
    for (int ks = 0; ks < 4; ks++) {
        const int kk = ks * 16;
        uint32_t ah[4][4], al[4][4], bh[4][2], bl[4][2];
        #pragma unroll
        for (int mi = 0; mi < 4; mi++) {
            uint32_t off = ((m0 + mi * 16 + ar) * ASTR + kk + ac) * 2;
            LDSM_X4(ah[mi][0], ah[mi][1], ah[mi][2], ah[mi][3], smAh + off);
            LDSM_X4(al[mi][0], al[mi][1], al[mi][2], al[mi][3], smAl + off);
        }
        #pragma unroll
        for (int ni = 0; ni < 4; ni++) {
            uint32_t off = ((kk + ar) * WSTR + n0 + ni * 8) * 2;
            LDSM_X2T(bh[ni][0], bh[ni][1], smWh + off);
            LDSM_X2T(bl[ni][0], bl[ni][1], smWl + off);
        }
        #pragma unroll
        for (int mi = 0; mi < 4; mi++)
            #pragma unroll
            for (int ni = 0; ni < 4; ni++) {
                MMA16816(acc[mi][ni], ah[mi], bh[ni]);
                MMA16816(acc[mi][ni], ah[mi], bl[ni]);
                MMA16816(acc[mi][ni], al[mi], bh[ni]);
            }
    }
}

__global__ __launch_bounds__(256) void gemm_mma_kernel(
    const bf16* __restrict__ Ah, const bf16* __restrict__ Al,
    const bf16* __restrict__ Wh, const bf16* __restrict__ Wl,
    const float* __restrict__ bias, float* __restrict__ C,
    bf16* __restrict__ Chi, bf16* __restrict__ Clo,
    int nmat, size_t strideA, size_t strideW, int outmode)
{
    extern __shared__ char smc[];
    const uint32_t smb = smem_u32(smc);
    float* s_bias = (float*)smc;

    const int tid = threadIdx.x;
    const int lane = tid & 31;
    const int wid = tid >> 5;
    const int wm = wid & 1;
    const int wn = wid >> 1;
    const int bm = blockIdx.y * 128;
    const int bn = blockIdx.x * 128;

    if (tid < 128) {
        float bs = 0.f;
        for (int n = 0; n < nmat; n++) bs += bias[(size_t)n * C_ + bn + tid];
        s_bias[tid] = bs;
    }

    float acc[4][4][4];
    #pragma unroll
    for (int mi = 0; mi < 4; mi++)
        #pragma unroll
        for (int ni = 0; ni < 4; ni++)
            #pragma unroll
            for (int r = 0; r < 4; r++) acc[mi][ni][r] = 0.f;

    const int NC = nmat * (C_ / BKC);

    load_chunk(smb + SMB_BUF, Ah, Al, Wh, Wl, bm, bn, 0, tid);
    CP_COMMIT();

    for (int c = 0; c < NC; c++) {
        if (c + 1 < NC) {
            int nm = (c + 1) >> 4;
            int k0 = ((c + 1) & 15) * BKC;
            load_chunk(smb + SMB_BUF + ((c + 1) & 1) * BUF_BYTES,
                       Ah + (size_t)nm * strideA, Al + (size_t)nm * strideA,
                       Wh + (size_t)nm * strideW, Wl + (size_t)nm * strideW,
                       bm, bn, k0, tid);
            CP_COMMIT();
            CP_WAIT(1);
        } else {
            CP_WAIT(0);
        }
        __syncthreads();
        compute_chunk(smb + SMB_BUF + (c & 1) * BUF_BYTES, wm, wn, lane, acc);
        __syncthreads();
    }

    const int r0 = bm + wm * 64 + (lane >> 2);
    const int c0rel = wn * 32 + 2 * (lane & 3);
    #pragma unroll
    for (int mi = 0; mi < 4; mi++) {
        #pragma unroll
        for (int ni = 0; ni < 4; ni++) {
            int crel = c0rel + ni * 8;
            float b0 = s_bias[crel], b1 = s_bias[crel + 1];
            int row = r0 + mi * 16;
            float a0 = acc[mi][ni][0] + b0, a1 = acc[mi][ni][1] + b1;
            float a2 = acc[mi][ni][2] + b0, a3 = acc[mi][ni][3] + b1;
            if (outmode == 0) {
                *(float2*)&C[(size_t)row * C_ + bn + crel] = make_float2(a0, a1);
                *(float2*)&C[(size_t)(row + 8) * C_ + bn + crel] = make_float2(a2, a3);
            } else {
                uint32_t h0, l0, h1, l1;
                split2(a0, a1, h0, l0);
                split2(a2, a3, h1, l1);
                *(uint32_t*)&Chi[(size_t)row * C_ + bn + crel] = h0;
                *(uint32_t*)&Clo[(size_t)row * C_ + bn + crel] = l0;
                *(uint32_t*)&Chi[(size_t)(row + 8) * C_ + bn + crel] = h1;
                *(uint32_t*)&Clo[(size_t)(row + 8) * C_ + bn + crel] = l1;
            }
        }
    }
}

// ============================================================================
// Flash attention v2: register-resident softmax (FA2 layout reuse).
// CTA: 128 q-rows, kv chunks of 64, 8 warps (16 q-rows each).
// S C-fragments are repacked in registers into PV A-fragments; mask/dist
// loaded per-lane from global; row stats via shfl within the 4-lane quad.
// Smem: Q hi/lo + double-buffered K/V hi/lo only.
// ============================================================================
#define FQ 128
#define FS 64
#define FSTR 72
#define OFF_QH 0
#define OFF_QL 18432
#define OFF_BUF 36864
#define KV_BUF_BYTES 36864
#define FLASH_SMEM (OFF_BUF + 2 * KV_BUF_BYTES)   // 110592

__global__ __launch_bounds__(256) void flash_mma_kernel(
    const bf16* __restrict__ Qh, const bf16* __restrict__ Ql,
    const bf16* __restrict__ Kh, const bf16* __restrict__ Kl,
    const bf16* __restrict__ Vh, const bf16* __restrict__ Vl,
    const int* __restrict__ mask, const float* __restrict__ dist,
    bf16* __restrict__ Ohi, bf16* __restrict__ Olo)
{
    extern __shared__ char smc[];
    const uint32_t smb = smem_u32(smc);

    const int bh  = blockIdx.x;
    const int b   = bh >> 4;
    const int h   = bh & 15;
    const int t10 = blockIdx.y * FQ;
    const int tid = threadIdx.x;
    const int lane = tid & 31;
    const int wid = tid >> 5;
    const int m0 = wid * 16;
    const int g  = lane >> 2;            // row within 8
    const int c2 = (lane & 3) * 2;       // col pair base

    // global q rows owned by this lane
    const int qr0 = t10 + m0 + g;
    const int qr1 = qr0 + 8;
    const int* mrow0 = &mask[(size_t)(b * T_ + qr0) * T_];
    const int* mrow1 = &mask[(size_t)(b * T_ + qr1) * T_];
    const float* drow0 = &dist[(size_t)(b * T_ + qr0) * T_];
    const float* drow1 = &dist[(size_t)(b * T_ + qr1) * T_];

    // ---- load Q tile (128 x 64, hi/lo) via cp.async ----
    #pragma unroll
    for (int v = 0; v < 4; v++) {
        int idx = tid + v * 256;
        int r = idx >> 3, c = idx & 7;
        size_t go = (size_t)(b * T_ + t10 + r) * C_ + h * HD_ + c * 8;
        uint32_t so = smb + r * (FSTR * 2) + c * 16;
        CP_ASYNC16(so + OFF_QH, Qh + go);
        CP_ASYNC16(so + OFF_QL, Ql + go);
    }
    CP_COMMIT();

    // ---- preload kv chunk 0 ----
    #pragma unroll
    for (int v = 0; v < 2; v++) {
        int idx = tid + v * 256;
        int r = idx >> 3, c = idx & 7;
        size_t go = (size_t)(b * T_ + r) * C_ + h * HD_ + c * 8;
        uint32_t so = smb + OFF_BUF + r * (FSTR * 2) + c * 16;
        CP_ASYNC16(so,         Kh + go);
        CP_ASYNC16(so + 9216,  Kl + go);
        CP_ASYNC16(so + 18432, Vh + go);
        CP_ASYNC16(so + 27648, Vl + go);
    }
    CP_COMMIT();

    float mstat0 = -3.0e38f, mstat1 = -3.0e38f;
    float lstat0 = 0.f, lstat1 = 0.f;

    float oacc[8][4];
    #pragma unroll
    for (int ni = 0; ni < 8; ni++)
        #pragma unroll
        for (int r = 0; r < 4; r++) oacc[ni][r] = 0.f;

    const int NITER = T_ / FS;           // 32

    for (int it = 0; it < NITER; it++) {
        if (it + 1 < NITER) {
            int s0n = (it + 1) * FS;
            uint32_t bb = smb + OFF_BUF + ((it + 1) & 1) * KV_BUF_BYTES;
            #pragma unroll
            for (int v = 0; v < 2; v++) {
                int idx = tid + v * 256;
                int r = idx >> 3, c = idx & 7;
                size_t go = (size_t)(b * T_ + s0n + r) * C_ + h * HD_ + c * 8;
                uint32_t so = bb + r * (FSTR * 2) + c * 16;
                CP_ASYNC16(so,         Kh + go);
                CP_ASYNC16(so + 9216,  Kl + go);
                CP_ASYNC16(so + 18432, Vh + go);
                CP_ASYNC16(so + 27648, Vl + go);
            }
            CP_COMMIT();
            CP_WAIT(1);
        } else {
            CP_WAIT(0);
        }
        __syncthreads();

        const int s0 = it * FS;
        const uint32_t bb = smb + OFF_BUF + (it & 1) * KV_BUF_BYTES;
        const uint32_t smKh = bb, smKl = bb + 9216;
        const uint32_t smVh = bb + 18432, smVl = bb + 27648;

        // ---- S = Q K^T (hi*hi + hi*lo + lo*hi) ----
        float sacc[8][4];
        #pragma unroll
        for (int ni = 0; ni < 8; ni++)
            #pragma unroll
            for (int r = 0; r < 4; r++) sacc[ni][r] = 0.f;

        #pragma unroll
        for (int ks = 0; ks < 4; ks++) {
            const int k0 = ks * 16;
            uint32_t qh[4], ql[4];
            uint32_t aoff = ((m0 + (lane & 15)) * FSTR + k0 + ((lane >> 4) << 3)) * 2;
            LDSM_X4(qh[0], qh[1], qh[2], qh[3], smb + OFF_QH + aoff);
            LDSM_X4(ql[0], ql[1], ql[2], ql[3], smb + OFF_QL + aoff);
            #pragma unroll
            for (int ni = 0; ni < 8; ni++) {
                uint32_t kbh[2], kbl[2];
                uint32_t boff = ((ni * 8 + (lane & 7)) * FSTR + k0 +
                                 ((lane >> 3) & 1) * 8) * 2;
                LDSM_X2(kbh[0], kbh[1], smKh + boff);
                LDSM_X2(kbl[0], kbl[1], smKl + boff);
                MMA16816(sacc[ni], qh, kbh);
                MMA16816(sacc[ni], qh, kbl);
                MMA16816(sacc[ni], ql, kbh);
            }
        }

        // ---- scale + mask (registers; per-lane global loads) ----
        #pragma unroll
        for (int ni = 0; ni < 8; ni++) {
            int s = s0 + ni * 8 + c2;
            int2 mk0 = *(const int2*)&mrow0[s];
            int2 mk1 = *(const int2*)&mrow1[s];
            sacc[ni][0] = mk0.x ? sacc[ni][0] * 0.125f : NEG_;
            sacc[ni][1] = mk0.y ? sacc[ni][1] * 0.125f : NEG_;
            sacc[ni][2] = mk1.x ? sacc[ni][2] * 0.125f : NEG_;
            sacc[ni][3] = mk1.y ? sacc[ni][3] * 0.125f : NEG_;
        }

        // ---- row max (regs + 2 shfl) ----
        float mx0 = -3.0e38f, mx1 = -3.0e38f;
        #pragma unroll
        for (int ni = 0; ni < 8; ni++) {
            mx0 = fmaxf(mx0, fmaxf(sacc[ni][0], sacc[ni][1]));
            mx1 = fmaxf(mx1, fmaxf(sacc[ni][2], sacc[ni][3]));
        }
        mx0 = fmaxf(mx0, __shfl_xor_sync(0xffffffff, mx0, 1));
        mx0 = fmaxf(mx0, __shfl_xor_sync(0xffffffff, mx0, 2));
        mx1 = fmaxf(mx1, __shfl_xor_sync(0xffffffff, mx1, 1));
        mx1 = fmaxf(mx1, __shfl_xor_sync(0xffffffff, mx1, 2));

        float mnew0 = fmaxf(mstat0, mx0);
        float mnew1 = fmaxf(mstat1, mx1);
        float fr0 = __expf(mstat0 - mnew0);
        float fr1 = __expf(mstat1 - mnew1);
        mstat0 = mnew0; mstat1 = mnew1;

        // ---- exp + row sum ----
        float sum0 = 0.f, sum1 = 0.f;
        #pragma unroll
        for (int ni = 0; ni < 8; ni++) {
            sacc[ni][0] = __expf(sacc[ni][0] - mnew0);
            sacc[ni][1] = __expf(sacc[ni][1] - mnew0);
            sacc[ni][2] = __expf(sacc[ni][2] - mnew1);
            sacc[ni][3] = __expf(sacc[ni][3] - mnew1);
            sum0 += sacc[ni][0] + sacc[ni][1];
            sum1 += sacc[ni][2] + sacc[ni][3];
        }
        sum0 += __shfl_xor_sync(0xffffffff, sum0, 1);
        sum0 += __shfl_xor_sync(0xffffffff, sum0, 2);
        sum1 += __shfl_xor_sync(0xffffffff, sum1, 1);
        sum1 += __shfl_xor_sync(0xffffffff, sum1, 2);
        lstat0 = lstat0 * fr0 + sum0;
        lstat1 = lstat1 * fr1 + sum1;

        // ---- dist modulation + pack P into PV A-fragments (hi/lo) ----
        uint32_t aH[4][4], aL[4][4];
        #pragma unroll
        for (int j = 0; j < 4; j++) {
            #pragma unroll
            for (int half = 0; half < 2; half++) {
                int ni = 2 * j + half;
                int s = s0 + ni * 8 + c2;
                float2 d0 = *(const float2*)&drow0[s];
                float2 d1 = *(const float2*)&drow1[s];
                float p00 = sacc[ni][0] * __expf(-4.0f * d0.x * d0.x);
                float p01 = sacc[ni][1] * __expf(-4.0f * d0.y * d0.y);
                float p10 = sacc[ni][2] * __expf(-4.0f * d1.x * d1.x);
                float p11 = sacc[ni][3] * __expf(-4.0f * d1.y * d1.y);
                split2(p00, p01, aH[j][half * 2 + 0], aL[j][half * 2 + 0]);
                split2(p10, p11, aH[j][half * 2 + 1], aL[j][half * 2 + 1]);
            }
        }

        // ---- rescale O, then O += P @ V (Ph*Vh + Ph*Vl + Pl*Vh) ----
        #pragma unroll
        for (int ni = 0; ni < 8; ni++) {
            oacc[ni][0] *= fr0; oacc[ni][1] *= fr0;
            oacc[ni][2] *= fr1; oacc[ni][3] *= fr1;
        }
        #pragma unroll
        for (int j = 0; j < 4; j++) {
            #pragma unroll
            for (int ni = 0; ni < 8; ni++) {
                uint32_t vbh[2], vbl[2];
                uint32_t boff = ((j * 16 + (lane & 15)) * FSTR + ni * 8) * 2;
                LDSM_X2T(vbh[0], vbh[1], smVh + boff);
                LDSM_X2T(vbl[0], vbl[1], smVl + boff);
                MMA16816(oacc[ni], aH[j], vbh);
                MMA16816(oacc[ni], aH[j], vbl);
                MMA16816(oacc[ni], aL[j], vbh);
            }
        }
        __syncthreads();
    }

    // ---- epilogue: /l, write bf16 hi/lo ----
    {
        float inv0 = 1.0f / lstat0;
        float inv1 = 1.0f / lstat1;
        size_t row0 = (size_t)(b * T_ + qr0) * C_ + h * HD_;
        size_t row1 = (size_t)(b * T_ + qr1) * C_ + h * HD_;
        #pragma unroll
        for (int ni = 0; ni < 8; ni++) {
            int c = ni * 8 + c2;
            uint32_t h0, l0, h1, l1;
            split2(oacc[ni][0] * inv0, oacc[ni][1] * inv0, h0, l0);
            split2(oacc[ni][2] * inv1, oacc[ni][3] * inv1, h1, l1);
            *(uint32_t*)&Ohi[row0 + c] = h0;
            *(uint32_t*)&Olo[row0 + c] = l0;
            *(uint32_t*)&Ohi[row1 + c] = h1;
            *(uint32_t*)&Olo[row1 + c] = l1;
        }
    }
}

// ============================================================================
// Launch
// ============================================================================
extern "C" void kernel_launch(void* const* d_in, const int* in_sizes, int n_in,
                              void* d_out, int out_size)
{
    const float* x_q  = (const float*)d_in[0];
    const float* x_r  = (const float*)d_in[1];
    const float* y    = (const float*)d_in[2];
    const int*   mask = (const int*)  d_in[3];
    const float* dist = (const float*)d_in[4];
    const float* Wq   = (const float*)d_in[5];
    const float* bq   = (const float*)d_in[6];
    const float* Wk   = (const float*)d_in[7];
    const float* bk   = (const float*)d_in[8];
    const float* Wv   = (const float*)d_in[9];
    const float* bv   = (const float*)d_in[10];
    const float* Wp   = (const float*)d_in[11];
    const float* bp   = (const float*)d_in[12];
    float* out = (float*)d_out;

    bf16 *qh, *ql, *kh, *kl, *vh, *vl;
    bf16 *xqh, *xql, *xrh, *xrl, *yh, *yl, *Oh, *Ol;
    bf16 *wqh, *wql, *wkh, *wkl, *wvh, *wvl, *wph, *wpl;
    cudaGetSymbolAddress((void**)&qh,  g_Qh);
    cudaGetSymbolAddress((void**)&ql,  g_Ql);
    cudaGetSymbolAddress((void**)&kh,  g_Kh);
    cudaGetSymbolAddress((void**)&kl,  g_Kl);
    cudaGetSymbolAddress((void**)&vh,  g_Vh);
    cudaGetSymbolAddress((void**)&vl,  g_Vl);
    cudaGetSymbolAddress((void**)&xqh, g_xqh);
    cudaGetSymbolAddress((void**)&xql, g_xql);
    cudaGetSymbolAddress((void**)&xrh, g_xrh);
    cudaGetSymbolAddress((void**)&xrl, g_xrl);
    cudaGetSymbolAddress((void**)&yh,  g_yh);
    cudaGetSymbolAddress((void**)&yl,  g_yl);
    cudaGetSymbolAddress((void**)&Oh,  g_Oh);
    cudaGetSymbolAddress((void**)&Ol,  g_Ol);
    cudaGetSymbolAddress((void**)&wqh, g_Wqh);
    cudaGetSymbolAddress((void**)&wql, g_Wql);
    cudaGetSymbolAddress((void**)&wkh, g_Wkh);
    cudaGetSymbolAddress((void**)&wkl, g_Wkl);
    cudaGetSymbolAddress((void**)&wvh, g_Wvh);
    cudaGetSymbolAddress((void**)&wvl, g_Wvl);
    cudaGetSymbolAddress((void**)&wph, g_Wph);
    cudaGetSymbolAddress((void**)&wpl, g_Wpl);

    cudaFuncSetAttribute(gemm_mma_kernel,
                         cudaFuncAttributeMaxDynamicSharedMemorySize, GEMM_SMEM);
    cudaFuncSetAttribute(flash_mma_kernel,
                         cudaFuncAttributeMaxDynamicSharedMemorySize, FLASH_SMEM);

    // ---- split fp32 inputs -> bf16 hi/lo ----
    const int MC4 = M_ * C_ / 4;
    const int CC4 = C_ * C_ / 4;
    split_kernel<<<MC4 / 256, 256>>>((const float4*)x_q, (uint2*)xqh, (uint2*)xql, MC4);
    split_kernel<<<MC4 / 256, 256>>>((const float4*)x_r, (uint2*)xrh, (uint2*)xrl, MC4);
    split_kernel<<<NI_ * MC4 / 256, 256>>>((const float4*)y, (uint2*)yh, (uint2*)yl, NI_ * MC4);
    split_kernel<<<CC4 / 256, 256>>>((const float4*)Wq, (uint2*)wqh, (uint2*)wql, CC4);
    split_kernel<<<CC4 / 256, 256>>>((const float4*)Wk, (uint2*)wkh, (uint2*)wkl, CC4);
    split_kernel<<<NI_ * CC4 / 256, 256>>>((const float4*)Wv, (uint2*)wvh, (uint2*)wvl, NI_ * CC4);
    split_kernel<<<CC4 / 256, 256>>>((const float4*)Wp, (uint2*)wph, (uint2*)wpl, CC4);

    dim3 gblk(256);
    dim3 ggrd(C_ / 128, M_ / 128);

    // projections -> bf16 hi/lo outputs
    gemm_mma_kernel<<<ggrd, gblk, GEMM_SMEM>>>(xqh, xql, wqh, wql, bq,
                                               nullptr, qh, ql, 1, 0, 0, 1);
    gemm_mma_kernel<<<ggrd, gblk, GEMM_SMEM>>>(xrh, xrl, wkh, wkl, bk,
                                               nullptr, kh, kl, 1, 0, 0, 1);
    gemm_mma_kernel<<<ggrd, gblk, GEMM_SMEM>>>(yh, yl, wvh, wvl, bv,
                                               nullptr, vh, vl, NI_,
                                               (size_t)M_ * C_, (size_t)C_ * C_, 1);

    // flash attention
    dim3 fgrd(B_ * H_, T_ / FQ);         // (32, 16)
    flash_mma_kernel<<<fgrd, 256, FLASH_SMEM>>>(qh, ql, kh, kl, vh, vl,
                                                mask, dist, Oh, Ol);

    // out projection -> fp32
    gemm_mma_kernel<<<ggrd, gblk, GEMM_SMEM>>>(Oh, Ol, wph, wpl, bp,
                                               out, nullptr, nullptr, 1, 0, 0, 0);
}

// round 10
// speedup vs baseline: 2.6820x; 1.1434x over previous
#include <cuda_runtime.h>
#include <cuda_bf16.h>
#include <cstdint>

// Problem shape (fixed by dataset)
#define B_  2
#define T_  2048
#define C_  1024
#define H_  16
#define HD_ 64
#define NI_ 3
#define M_  (B_ * T_)
#define NEG_ (-1e9f)

typedef __nv_bfloat16 bf16;

// -------- scratch (device globals; no allocation allowed) --------
__device__ bf16 g_Qh[(size_t)M_ * C_],       g_Ql[(size_t)M_ * C_];
__device__ bf16 g_Kh[(size_t)M_ * C_],       g_Kl[(size_t)M_ * C_];
__device__ bf16 g_Vh[(size_t)M_ * C_],       g_Vl[(size_t)M_ * C_];
__device__ bf16 g_xqh[(size_t)M_ * C_],      g_xql[(size_t)M_ * C_];
__device__ bf16 g_xrh[(size_t)M_ * C_],      g_xrl[(size_t)M_ * C_];
__device__ bf16 g_yh [(size_t)NI_ * M_ * C_], g_yl [(size_t)NI_ * M_ * C_];
__device__ bf16 g_Oh [(size_t)M_ * C_],      g_Ol [(size_t)M_ * C_];
__device__ bf16 g_Wqh[(size_t)C_ * C_],      g_Wql[(size_t)C_ * C_];
__device__ bf16 g_Wkh[(size_t)C_ * C_],      g_Wkl[(size_t)C_ * C_];
__device__ bf16 g_Wvh[(size_t)NI_ * C_ * C_], g_Wvl[(size_t)NI_ * C_ * C_];
__device__ bf16 g_Wph[(size_t)C_ * C_],      g_Wpl[(size_t)C_ * C_];
__device__ float g_wm[(size_t)B_ * T_ * T_];  // mask? exp(-4d^2) : -1

// ============================================================================
// helpers
// ============================================================================
__device__ __forceinline__ uint32_t smem_u32(const void* p) {
    uint32_t a;
    asm("{ .reg .u64 t; cvta.to.shared.u64 t, %1; cvt.u32.u64 %0, t; }"
        : "=r"(a) : "l"(p));
    return a;
}
__device__ __forceinline__ uint32_t pack_bf16(float a, float b) {
    uint32_t ua = __bfloat16_as_ushort(__float2bfloat16_rn(a));
    uint32_t ub = __bfloat16_as_ushort(__float2bfloat16_rn(b));
    return (ub << 16) | ua;
}
__device__ __forceinline__ void split2(float a, float b, uint32_t& hi, uint32_t& lo) {
    bf16 h0 = __float2bfloat16_rn(a);
    bf16 h1 = __float2bfloat16_rn(b);
    hi = ((uint32_t)__bfloat16_as_ushort(h1) << 16) | __bfloat16_as_ushort(h0);
    lo = pack_bf16(a - __bfloat162float(h0), b - __bfloat162float(h1));
}

#define CP_ASYNC16(dst, src) \
    asm volatile("cp.async.cg.shared.global [%0], [%1], 16;" :: "r"(dst), "l"(src))
#define CP_COMMIT() asm volatile("cp.async.commit_group;" ::: "memory")
#define CP_WAIT(n)  asm volatile("cp.async.wait_group %0;" :: "n"(n) : "memory")

#define LDSM_X4(r0, r1, r2, r3, addr) \
    asm volatile("ldmatrix.sync.aligned.m8n8.x4.shared.b16 {%0,%1,%2,%3}, [%4];" \
                 : "=r"(r0), "=r"(r1), "=r"(r2), "=r"(r3) : "r"(addr))
#define LDSM_X4T(r0, r1, r2, r3, addr) \
    asm volatile("ldmatrix.sync.aligned.m8n8.x4.trans.shared.b16 {%0,%1,%2,%3}, [%4];" \
                 : "=r"(r0), "=r"(r1), "=r"(r2), "=r"(r3) : "r"(addr))

#define MMA16816(d, a, b0, b1) \
    asm volatile("mma.sync.aligned.m16n8k16.row.col.f32.bf16.bf16.f32 " \
                 "{%0,%1,%2,%3}, {%4,%5,%6,%7}, {%8,%9}, {%0,%1,%2,%3};" \
                 : "+f"((d)[0]), "+f"((d)[1]), "+f"((d)[2]), "+f"((d)[3]) \
                 : "r"((a)[0]), "r"((a)[1]), "r"((a)[2]), "r"((a)[3]), \
                   "r"(b0), "r"(b1))

// ============================================================================
// split kernel: fp32 -> bf16 hi + bf16 lo (residual)
// ============================================================================
__global__ __launch_bounds__(256) void split_kernel(
    const float4* __restrict__ in, uint2* __restrict__ hi,
    uint2* __restrict__ lo, int n4)
{
    int i = blockIdx.x * 256 + threadIdx.x;
    if (i >= n4) return;
    float4 f = in[i];
    uint32_t h0, l0, h1, l1;
    split2(f.x, f.y, h0, l0);
    split2(f.z, f.w, h1, l1);
    hi[i] = make_uint2(h0, h1);
    lo[i] = make_uint2(l0, l1);
}

// ============================================================================
// wm kernel: wm = mask ? exp(-4 d^2) : -1
// ============================================================================
__global__ __launch_bounds__(256) void wm_kernel(
    const int2* __restrict__ mask, const float2* __restrict__ dist,
    float2* __restrict__ wm, int n2)
{
    int i = blockIdx.x * 256 + threadIdx.x;
    if (i >= n2) return;
    int2 m = mask[i];
    float2 d = dist[i];
    float2 w;
    w.x = m.x ? __expf(-4.0f * d.x * d.x) : -1.0f;
    w.y = m.y ? __expf(-4.0f * d.y * d.y) : -1.0f;
    wm[i] = w;
}

// ============================================================================
// bf16 split GEMM via mma.sync.m16n8k16, 3-stage cp.async pipeline.
//   C = sum_n A_n[M,K] @ W_n[K,N] + sum_n bias_n[N]
// outmode 0: fp32 to C.  outmode 1: bf16 hi/lo to Chi/Clo.
// ============================================================================
#define ASTR 72
#define WSTR 136
#define BKC  64
#define A_BYTES (128 * ASTR * 2)
#define W_BYTES (64 * WSTR * 2)
#define BUF_BYTES (2 * A_BYTES + 2 * W_BYTES)      // 71680
#define SMB_BUF 1024
#define GEMM_SMEM (SMB_BUF + 3 * BUF_BYTES)        // 216064

__device__ __forceinline__ void load_chunk(
    uint32_t sbuf, const bf16* __restrict__ Ah, const bf16* __restrict__ Al,
    const bf16* __restrict__ Wh, const bf16* __restrict__ Wl,
    int bm, int bn, int k0, int tid)
{
    #pragma unroll
    for (int v = 0; v < 4; v++) {
        int idx = tid + v * 256;
        int r = idx >> 3, c = idx & 7;
        size_t go = (size_t)(bm + r) * C_ + k0 + c * 8;
        uint32_t so = sbuf + r * (ASTR * 2) + c * 16;
        CP_ASYNC16(so, Ah + go);
        CP_ASYNC16(so + A_BYTES, Al + go);
    }
    #pragma unroll
    for (int v = 0; v < 4; v++) {
        int idx = tid + v * 256;
        int r = idx >> 4, c = idx & 15;
        size_t go = (size_t)(k0 + r) * C_ + bn + c * 8;
        uint32_t so = sbuf + 2 * A_BYTES + r * (WSTR * 2) + c * 16;
        CP_ASYNC16(so, Wh + go);
        CP_ASYNC16(so + W_BYTES, Wl + go);
    }
}

__device__ __forceinline__ void compute_chunk(
    uint32_t sbuf, int wm_, int wn, int lane, float acc[4][4][4])
{
    const uint32_t smAh = sbuf;
    const uint32_t smAl = sbuf + A_BYTES;
    const uint32_t smWh = sbuf + 2 * A_BYTES;
    const uint32_t smWl = sbuf + 2 * A_BYTES + W_BYTES;
    const int m0 = wm_ * 64, n0 = wn * 32;
    const int ar = lane & 15;
    const int ac = (lane >> 4) << 3;

    #pragma unroll
    for (int ks = 0; ks < 4; ks++) {
        const int kk = ks * 16;
        uint32_t ah[4][4], al[4][4], bh[2][4], bl[2][4];
        #pragma unroll
        for (int mi = 0; mi < 4; mi++) {
            uint32_t off = ((m0 + mi * 16 + ar) * ASTR + kk + ac) * 2;
            LDSM_X4(ah[mi][0], ah[mi][1], ah[mi][2], ah[mi][3], smAh + off);
            LDSM_X4(al[mi][0], al[mi][1], al[mi][2], al[mi][3], smAl + off);
        }
        // paired trans loads: x4 = two n8 fragments
        #pragma unroll
        for (int nj = 0; nj < 2; nj++) {
            uint32_t off = ((kk + ar) * WSTR + n0 + nj * 16 +
                            ((lane >> 4) & 1) * 8) * 2;
            LDSM_X4T(bh[nj][0], bh[nj][1], bh[nj][2], bh[nj][3], smWh + off);
            LDSM_X4T(bl[nj][0], bl[nj][1], bl[nj][2], bl[nj][3], smWl + off);
        }
        #pragma unroll
        for (int mi = 0; mi < 4; mi++)
            #pragma unroll
            for (int nj = 0; nj < 2; nj++) {
                MMA16816(acc[mi][nj * 2],     ah[mi], bh[nj][0], bh[nj][1]);
                MMA16816(acc[mi][nj * 2],     ah[mi], bl[nj][0], bl[nj][1]);
                MMA16816(acc[mi][nj * 2],     al[mi], bh[nj][0], bh[nj][1]);
                MMA16816(acc[mi][nj * 2 + 1], ah[mi], bh[nj][2], bh[nj][3]);
                MMA16816(acc[mi][nj * 2 + 1], ah[mi], bl[nj][2], bl[nj][3]);
                MMA16816(acc[mi][nj * 2 + 1], al[mi], bh[nj][2], bh[nj][3]);
            }
    }
}

__global__ __launch_bounds__(256) void gemm_mma_kernel(
    const bf16* __restrict__ Ah, const bf16* __restrict__ Al,
    const bf16* __restrict__ Wh, const bf16* __restrict__ Wl,
    const float* __restrict__ bias, float* __restrict__ C,
    bf16* __restrict__ Chi, bf16* __restrict__ Clo,
    int nmat, size_t strideA, size_t strideW, int outmode)
{
    extern __shared__ char smc[];
    const uint32_t smb = smem_u32(smc);
    float* s_bias = (float*)smc;

    const int tid = threadIdx.x;
    const int lane = tid & 31;
    const int wid = tid >> 5;
    const int wm_ = wid & 1;
    const int wn = wid >> 1;
    const int bm = blockIdx.y * 128;
    const int bn = blockIdx.x * 128;

    if (tid < 128) {
        float bs = 0.f;
        for (int n = 0; n < nmat; n++) bs += bias[(size_t)n * C_ + bn + tid];
        s_bias[tid] = bs;
    }

    float acc[4][4][4];
    #pragma unroll
    for (int mi = 0; mi < 4; mi++)
        #pragma unroll
        for (int ni = 0; ni < 4; ni++)
            #pragma unroll
            for (int r = 0; r < 4; r++) acc[mi][ni][r] = 0.f;

    const int NC = nmat * (C_ / BKC);

    // prologue: chunks 0, 1
    load_chunk(smb + SMB_BUF, Ah, Al, Wh, Wl, bm, bn, 0, tid);
    CP_COMMIT();
    {
        int nm = 1 >> 4, k0 = (1 & 15) * BKC;
        load_chunk(smb + SMB_BUF + BUF_BYTES,
                   Ah + (size_t)nm * strideA, Al + (size_t)nm * strideA,
                   Wh + (size_t)nm * strideW, Wl + (size_t)nm * strideW,
                   bm, bn, k0, tid);
        CP_COMMIT();
    }

    for (int c = 0; c < NC; c++) {
        if (c + 1 < NC) { CP_WAIT(1); } else { CP_WAIT(0); }
        __syncthreads();
        if (c + 2 < NC) {
            int cc = c + 2;
            int nm = cc >> 4;
            int k0 = (cc & 15) * BKC;
            load_chunk(smb + SMB_BUF + (cc % 3) * BUF_BYTES,
                       Ah + (size_t)nm * strideA, Al + (size_t)nm * strideA,
                       Wh + (size_t)nm * strideW, Wl + (size_t)nm * strideW,
                       bm, bn, k0, tid);
            CP_COMMIT();
        }
        compute_chunk(smb + SMB_BUF + (c % 3) * BUF_BYTES, wm_, wn, lane, acc);
    }

    const int r0 = bm + wm_ * 64 + (lane >> 2);
    const int c0rel = wn * 32 + 2 * (lane & 3);
    #pragma unroll
    for (int mi = 0; mi < 4; mi++) {
        #pragma unroll
        for (int ni = 0; ni < 4; ni++) {
            int crel = c0rel + ni * 8;
            float b0 = s_bias[crel], b1 = s_bias[crel + 1];
            int row = r0 + mi * 16;
            float a0 = acc[mi][ni][0] + b0, a1 = acc[mi][ni][1] + b1;
            float a2 = acc[mi][ni][2] + b0, a3 = acc[mi][ni][3] + b1;
            if (outmode == 0) {
                *(float2*)&C[(size_t)row * C_ + bn + crel] = make_float2(a0, a1);
                *(float2*)&C[(size_t)(row + 8) * C_ + bn + crel] = make_float2(a2, a3);
            } else {
                uint32_t h0, l0, h1, l1;
                split2(a0, a1, h0, l0);
                split2(a2, a3, h1, l1);
                *(uint32_t*)&Chi[(size_t)row * C_ + bn + crel] = h0;
                *(uint32_t*)&Clo[(size_t)row * C_ + bn + crel] = l0;
                *(uint32_t*)&Chi[(size_t)(row + 8) * C_ + bn + crel] = h1;
                *(uint32_t*)&Clo[(size_t)(row + 8) * C_ + bn + crel] = l1;
            }
        }
    }
}

// ============================================================================
// Flash attention: register softmax + precomputed wm + 3-stage KV pipeline.
// CTA: 128 q-rows, kv chunks of 64, 8 warps (16 q-rows each).
// ============================================================================
#define FQ 128
#define FS 64
#define FSTR 72
#define OFF_QH 0
#define OFF_QL 18432
#define OFF_BUF 36864
#define KV_BUF_BYTES 36864
#define FLASH_SMEM (OFF_BUF + 3 * KV_BUF_BYTES)    // 147456

__device__ __forceinline__ void flash_load_kv(
    uint32_t bb, const bf16* __restrict__ Kh, const bf16* __restrict__ Kl,
    const bf16* __restrict__ Vh, const bf16* __restrict__ Vl,
    int b, int h, int s0, int tid)
{
    #pragma unroll
    for (int v = 0; v < 2; v++) {
        int idx = tid + v * 256;
        int r = idx >> 3, c = idx & 7;
        size_t go = (size_t)(b * T_ + s0 + r) * C_ + h * HD_ + c * 8;
        uint32_t so = bb + r * (FSTR * 2) + c * 16;
        CP_ASYNC16(so,         Kh + go);
        CP_ASYNC16(so + 9216,  Kl + go);
        CP_ASYNC16(so + 18432, Vh + go);
        CP_ASYNC16(so + 27648, Vl + go);
    }
}

__global__ __launch_bounds__(256) void flash_mma_kernel(
    const bf16* __restrict__ Qh, const bf16* __restrict__ Ql,
    const bf16* __restrict__ Kh, const bf16* __restrict__ Kl,
    const bf16* __restrict__ Vh, const bf16* __restrict__ Vl,
    const float* __restrict__ wm, bf16* __restrict__ Ohi,
    bf16* __restrict__ Olo)
{
    extern __shared__ char smc[];
    const uint32_t smb = smem_u32(smc);

    const int bh  = blockIdx.x;
    const int b   = bh >> 4;
    const int h   = bh & 15;
    const int t10 = blockIdx.y * FQ;
    const int tid = threadIdx.x;
    const int lane = tid & 31;
    const int wid = tid >> 5;
    const int m0 = wid * 16;
    const int g  = lane >> 2;
    const int c2 = (lane & 3) * 2;

    const int qr0 = t10 + m0 + g;
    const int qr1 = qr0 + 8;
    const float* wrow0 = &wm[(size_t)(b * T_ + qr0) * T_];
    const float* wrow1 = &wm[(size_t)(b * T_ + qr1) * T_];

    // ---- load Q tile ----
    #pragma unroll
    for (int v = 0; v < 4; v++) {
        int idx = tid + v * 256;
        int r = idx >> 3, c = idx & 7;
        size_t go = (size_t)(b * T_ + t10 + r) * C_ + h * HD_ + c * 8;
        uint32_t so = smb + r * (FSTR * 2) + c * 16;
        CP_ASYNC16(so + OFF_QH, Qh + go);
        CP_ASYNC16(so + OFF_QL, Ql + go);
    }
    CP_COMMIT();
    // ---- kv chunks 0, 1 ----
    flash_load_kv(smb + OFF_BUF, Kh, Kl, Vh, Vl, b, h, 0, tid);
    CP_COMMIT();
    flash_load_kv(smb + OFF_BUF + KV_BUF_BYTES, Kh, Kl, Vh, Vl, b, h, FS, tid);
    CP_COMMIT();

    float mstat0 = -3.0e38f, mstat1 = -3.0e38f;
    float lstat0 = 0.f, lstat1 = 0.f;

    float oacc[8][4];
    #pragma unroll
    for (int ni = 0; ni < 8; ni++)
        #pragma unroll
        for (int r = 0; r < 4; r++) oacc[ni][r] = 0.f;

    const int NITER = T_ / FS;           // 32

    for (int it = 0; it < NITER; it++) {
        if (it + 1 < NITER) { CP_WAIT(1); } else { CP_WAIT(0); }
        __syncthreads();
        if (it + 2 < NITER) {
            flash_load_kv(smb + OFF_BUF + ((it + 2) % 3) * KV_BUF_BYTES,
                          Kh, Kl, Vh, Vl, b, h, (it + 2) * FS, tid);
            CP_COMMIT();
        }

        const int s0 = it * FS;
        const uint32_t bb = smb + OFF_BUF + (it % 3) * KV_BUF_BYTES;
        const uint32_t smKh = bb, smKl = bb + 9216;
        const uint32_t smVh = bb + 18432, smVl = bb + 27648;

        // ---- S = Q K^T (hi*hi + hi*lo + lo*hi), paired K x4 loads ----
        float sacc[8][4];
        #pragma unroll
        for (int ni = 0; ni < 8; ni++)
            #pragma unroll
            for (int r = 0; r < 4; r++) sacc[ni][r] = 0.f;

        #pragma unroll
        for (int ks = 0; ks < 4; ks++) {
            const int k0 = ks * 16;
            uint32_t qh[4], ql[4];
            uint32_t aoff = ((m0 + (lane & 15)) * FSTR + k0 + ((lane >> 4) << 3)) * 2;
            LDSM_X4(qh[0], qh[1], qh[2], qh[3], smb + OFF_QH + aoff);
            LDSM_X4(ql[0], ql[1], ql[2], ql[3], smb + OFF_QL + aoff);
            #pragma unroll
            for (int nj = 0; nj < 4; nj++) {
                uint32_t kh4[4], kl4[4];
                uint32_t boff = ((nj * 16 + (lane & 7) + ((lane >> 4) << 3)) * FSTR +
                                 k0 + ((lane >> 3) & 1) * 8) * 2;
                LDSM_X4(kh4[0], kh4[1], kh4[2], kh4[3], smKh + boff);
                LDSM_X4(kl4[0], kl4[1], kl4[2], kl4[3], smKl + boff);
                MMA16816(sacc[nj * 2],     qh, kh4[0], kh4[1]);
                MMA16816(sacc[nj * 2],     qh, kl4[0], kl4[1]);
                MMA16816(sacc[nj * 2],     ql, kh4[0], kh4[1]);
                MMA16816(sacc[nj * 2 + 1], qh, kh4[2], kh4[3]);
                MMA16816(sacc[nj * 2 + 1], qh, kl4[2], kl4[3]);
                MMA16816(sacc[nj * 2 + 1], ql, kh4[2], kh4[3]);
            }
        }

        // ---- wm load: scale + mask via sign ----
        float wreg[8][4];
        #pragma unroll
        for (int ni = 0; ni < 8; ni++) {
            int s = s0 + ni * 8 + c2;
            float2 w0 = *(const float2*)&wrow0[s];
            float2 w1 = *(const float2*)&wrow1[s];
            wreg[ni][0] = w0.x; wreg[ni][1] = w0.y;
            wreg[ni][2] = w1.x; wreg[ni][3] = w1.y;
            sacc[ni][0] = w0.x > 0.f ? sacc[ni][0] * 0.125f : NEG_;
            sacc[ni][1] = w0.y > 0.f ? sacc[ni][1] * 0.125f : NEG_;
            sacc[ni][2] = w1.x > 0.f ? sacc[ni][2] * 0.125f : NEG_;
            sacc[ni][3] = w1.y > 0.f ? sacc[ni][3] * 0.125f : NEG_;
        }

        // ---- row max ----
        float mx0 = -3.0e38f, mx1 = -3.0e38f;
        #pragma unroll
        for (int ni = 0; ni < 8; ni++) {
            mx0 = fmaxf(mx0, fmaxf(sacc[ni][0], sacc[ni][1]));
            mx1 = fmaxf(mx1, fmaxf(sacc[ni][2], sacc[ni][3]));
        }
        mx0 = fmaxf(mx0, __shfl_xor_sync(0xffffffff, mx0, 1));
        mx0 = fmaxf(mx0, __shfl_xor_sync(0xffffffff, mx0, 2));
        mx1 = fmaxf(mx1, __shfl_xor_sync(0xffffffff, mx1, 1));
        mx1 = fmaxf(mx1, __shfl_xor_sync(0xffffffff, mx1, 2));

        float mnew0 = fmaxf(mstat0, mx0);
        float mnew1 = fmaxf(mstat1, mx1);
        float fr0 = __expf(mstat0 - mnew0);
        float fr1 = __expf(mstat1 - mnew1);
        mstat0 = mnew0; mstat1 = mnew1;

        // ---- exp + row sum ----
        float sum0 = 0.f, sum1 = 0.f;
        #pragma unroll
        for (int ni = 0; ni < 8; ni++) {
            sacc[ni][0] = __expf(sacc[ni][0] - mnew0);
            sacc[ni][1] = __expf(sacc[ni][1] - mnew0);
            sacc[ni][2] = __expf(sacc[ni][2] - mnew1);
            sacc[ni][3] = __expf(sacc[ni][3] - mnew1);
            sum0 += sacc[ni][0] + sacc[ni][1];
            sum1 += sacc[ni][2] + sacc[ni][3];
        }
        sum0 += __shfl_xor_sync(0xffffffff, sum0, 1);
        sum0 += __shfl_xor_sync(0xffffffff, sum0, 2);
        sum1 += __shfl_xor_sync(0xffffffff, sum1, 1);
        sum1 += __shfl_xor_sync(0xffffffff, sum1, 2);
        lstat0 = lstat0 * fr0 + sum0;
        lstat1 = lstat1 * fr1 + sum1;

        // ---- numerator modulation + pack P fragments (hi/lo) ----
        uint32_t aH[4][4], aL[4][4];
        #pragma unroll
        for (int j = 0; j < 4; j++) {
            #pragma unroll
            for (int half = 0; half < 2; half++) {
                int ni = 2 * j + half;
                float p00 = sacc[ni][0] * wreg[ni][0];
                float p01 = sacc[ni][1] * wreg[ni][1];
                float p10 = sacc[ni][2] * wreg[ni][2];
                float p11 = sacc[ni][3] * wreg[ni][3];
                split2(p00, p01, aH[j][half * 2 + 0], aL[j][half * 2 + 0]);
                split2(p10, p11, aH[j][half * 2 + 1], aL[j][half * 2 + 1]);
            }
        }

        // ---- rescale O, then O += P @ V (paired V x4 trans loads) ----
        #pragma unroll
        for (int ni = 0; ni < 8; ni++) {
            oacc[ni][0] *= fr0; oacc[ni][1] *= fr0;
            oacc[ni][2] *= fr1; oacc[ni][3] *= fr1;
        }
        #pragma unroll
        for (int j = 0; j < 4; j++) {
            #pragma unroll
            for (int nj = 0; nj < 4; nj++) {
                uint32_t vh4[4], vl4[4];
                uint32_t boff = ((j * 16 + (lane & 15)) * FSTR +
                                 (nj * 2 + ((lane >> 4) & 1)) * 8) * 2;
                LDSM_X4T(vh4[0], vh4[1], vh4[2], vh4[3], smVh + boff);
                LDSM_X4T(vl4[0], vl4[1], vl4[2], vl4[3], smVl + boff);
                MMA16816(oacc[nj * 2],     aH[j], vh4[0], vh4[1]);
                MMA16816(oacc[nj * 2],     aH[j], vl4[0], vl4[1]);
                MMA16816(oacc[nj * 2],     aL[j], vh4[0], vh4[1]);
                MMA16816(oacc[nj * 2 + 1], aH[j], vh4[2], vh4[3]);
                MMA16816(oacc[nj * 2 + 1], aH[j], vl4[2], vl4[3]);
                MMA16816(oacc[nj * 2 + 1], aL[j], vh4[2], vh4[3]);
            }
        }
    }

    // ---- epilogue: /l, write bf16 hi/lo ----
    {
        float inv0 = 1.0f / lstat0;
        float inv1 = 1.0f / lstat1;
        size_t row0 = (size_t)(b * T_ + qr0) * C_ + h * HD_;
        size_t row1 = (size_t)(b * T_ + qr1) * C_ + h * HD_;
        #pragma unroll
        for (int ni = 0; ni < 8; ni++) {
            int c = ni * 8 + c2;
            uint32_t h0, l0, h1, l1;
            split2(oacc[ni][0] * inv0, oacc[ni][1] * inv0, h0, l0);
            split2(oacc[ni][2] * inv1, oacc[ni][3] * inv1, h1, l1);
            *(uint32_t*)&Ohi[row0 + c] = h0;
            *(uint32_t*)&Olo[row0 + c] = l0;
            *(uint32_t*)&Ohi[row1 + c] = h1;
            *(uint32_t*)&Olo[row1 + c] = l1;
        }
    }
}

// ============================================================================
// Launch
// ============================================================================
extern "C" void kernel_launch(void* const* d_in, const int* in_sizes, int n_in,
                              void* d_out, int out_size)
{
    const float* x_q  = (const float*)d_in[0];
    const float* x_r  = (const float*)d_in[1];
    const float* y    = (const float*)d_in[2];
    const int*   mask = (const int*)  d_in[3];
    const float* dist = (const float*)d_in[4];
    const float* Wq   = (const float*)d_in[5];
    const float* bq   = (const float*)d_in[6];
    const float* Wk   = (const float*)d_in[7];
    const float* bk   = (const float*)d_in[8];
    const float* Wv   = (const float*)d_in[9];
    const float* bv   = (const float*)d_in[10];
    const float* Wp   = (const float*)d_in[11];
    const float* bp   = (const float*)d_in[12];
    float* out = (float*)d_out;

    bf16 *qh, *ql, *kh, *kl, *vh, *vl;
    bf16 *xqh, *xql, *xrh, *xrl, *yh, *yl, *Oh, *Ol;
    bf16 *wqh, *wql, *wkh, *wkl, *wvh, *wvl, *wph, *wpl;
    float* wmp;
    cudaGetSymbolAddress((void**)&qh,  g_Qh);
    cudaGetSymbolAddress((void**)&ql,  g_Ql);
    cudaGetSymbolAddress((void**)&kh,  g_Kh);
    cudaGetSymbolAddress((void**)&kl,  g_Kl);
    cudaGetSymbolAddress((void**)&vh,  g_Vh);
    cudaGetSymbolAddress((void**)&vl,  g_Vl);
    cudaGetSymbolAddress((void**)&xqh, g_xqh);
    cudaGetSymbolAddress((void**)&xql, g_xql);
    cudaGetSymbolAddress((void**)&xrh, g_xrh);
    cudaGetSymbolAddress((void**)&xrl, g_xrl);
    cudaGetSymbolAddress((void**)&yh,  g_yh);
    cudaGetSymbolAddress((void**)&yl,  g_yl);
    cudaGetSymbolAddress((void**)&Oh,  g_Oh);
    cudaGetSymbolAddress((void**)&Ol,  g_Ol);
    cudaGetSymbolAddress((void**)&wqh, g_Wqh);
    cudaGetSymbolAddress((void**)&wql, g_Wql);
    cudaGetSymbolAddress((void**)&wkh, g_Wkh);
    cudaGetSymbolAddress((void**)&wkl, g_Wkl);
    cudaGetSymbolAddress((void**)&wvh, g_Wvh);
    cudaGetSymbolAddress((void**)&wvl, g_Wvl);
    cudaGetSymbolAddress((void**)&wph, g_Wph);
    cudaGetSymbolAddress((void**)&wpl, g_Wpl);
    cudaGetSymbolAddress((void**)&wmp, g_wm);

    cudaFuncSetAttribute(gemm_mma_kernel,
                         cudaFuncAttributeMaxDynamicSharedMemorySize, GEMM_SMEM);
    cudaFuncSetAttribute(flash_mma_kernel,
                         cudaFuncAttributeMaxDynamicSharedMemorySize, FLASH_SMEM);

    // ---- split fp32 inputs -> bf16 hi/lo; build wm ----
    const int MC4 = M_ * C_ / 4;
    const int CC4 = C_ * C_ / 4;
    split_kernel<<<MC4 / 256, 256>>>((const float4*)x_q, (uint2*)xqh, (uint2*)xql, MC4);
    split_kernel<<<MC4 / 256, 256>>>((const float4*)x_r, (uint2*)xrh, (uint2*)xrl, MC4);
    split_kernel<<<NI_ * MC4 / 256, 256>>>((const float4*)y, (uint2*)yh, (uint2*)yl, NI_ * MC4);
    split_kernel<<<CC4 / 256, 256>>>((const float4*)Wq, (uint2*)wqh, (uint2*)wql, CC4);
    split_kernel<<<CC4 / 256, 256>>>((const float4*)Wk, (uint2*)wkh, (uint2*)wkl, CC4);
    split_kernel<<<NI_ * CC4 / 256, 256>>>((const float4*)Wv, (uint2*)wvh, (uint2*)wvl, NI_ * CC4);
    split_kernel<<<CC4 / 256, 256>>>((const float4*)Wp, (uint2*)wph, (uint2*)wpl, CC4);
    {
        const int n2 = B_ * T_ * T_ / 2;
        wm_kernel<<<(n2 + 255) / 256, 256>>>((const int2*)mask,
                                             (const float2*)dist,
                                             (float2*)wmp, n2);
    }

    dim3 gblk(256);
    dim3 ggrd(C_ / 128, M_ / 128);

    gemm_mma_kernel<<<ggrd, gblk, GEMM_SMEM>>>(xqh, xql, wqh, wql, bq,
                                               nullptr, qh, ql, 1, 0, 0, 1);
    gemm_mma_kernel<<<ggrd, gblk, GEMM_SMEM>>>(xrh, xrl, wkh, wkl, bk,
                                               nullptr, kh, kl, 1, 0, 0, 1);
    gemm_mma_kernel<<<ggrd, gblk, GEMM_SMEM>>>(yh, yl, wvh, wvl, bv,
                                               nullptr, vh, vl, NI_,
                                               (size_t)M_ * C_, (size_t)C_ * C_, 1);

    dim3 fgrd(B_ * H_, T_ / FQ);         // (32, 16)
    flash_mma_kernel<<<fgrd, 256, FLASH_SMEM>>>(qh, ql, kh, kl, vh, vl,
                                                wmp, Oh, Ol);

    gemm_mma_kernel<<<ggrd, gblk, GEMM_SMEM>>>(Oh, Ol, wph, wpl, bp,
                                               out, nullptr, nullptr, 1, 0, 0, 0);
}

// round 11
// speedup vs baseline: 4.0870x; 1.5238x over previous
#include <cuda_runtime.h>
#include <cuda_fp16.h>
#include <cstdint>

// Problem shape (fixed by dataset)
#define B_  2
#define T_  2048
#define C_  1024
#define H_  16
#define HD_ 64
#define NI_ 3
#define M_  (B_ * T_)
#define NEG_ (-1e9f)

typedef __half f16;

// -------- scratch (device globals; no allocation allowed) --------
__device__ f16 g_Qh[(size_t)M_ * C_],       g_Ql[(size_t)M_ * C_];
__device__ f16 g_Kh[(size_t)M_ * C_];
__device__ f16 g_Vh[(size_t)M_ * C_];
__device__ f16 g_xqh[(size_t)M_ * C_],      g_xql[(size_t)M_ * C_];
__device__ f16 g_xrh[(size_t)M_ * C_],      g_xrl[(size_t)M_ * C_];
__device__ f16 g_yh [(size_t)NI_ * M_ * C_], g_yl [(size_t)NI_ * M_ * C_];
__device__ f16 g_Oh [(size_t)M_ * C_],      g_Ol [(size_t)M_ * C_];
__device__ f16 g_Wqh[(size_t)C_ * C_];
__device__ f16 g_Wkh[(size_t)C_ * C_];
__device__ f16 g_Wvh[(size_t)NI_ * C_ * C_];
__device__ f16 g_Wph[(size_t)C_ * C_];
__device__ float g_wm[(size_t)B_ * T_ * T_];  // mask? exp(-4d^2) : -1

// ============================================================================
// helpers
// ============================================================================
__device__ __forceinline__ uint32_t smem_u32(const void* p) {
    uint32_t a;
    asm("{ .reg .u64 t; cvta.to.shared.u64 t, %1; cvt.u32.u64 %0, t; }"
        : "=r"(a) : "l"(p));
    return a;
}
__device__ __forceinline__ uint32_t pack_h2(float a, float b) {
    f16 h0 = __float2half_rn(a);
    f16 h1 = __float2half_rn(b);
    return ((uint32_t)__half_as_ushort(h1) << 16) | __half_as_ushort(h0);
}
__device__ __forceinline__ void split2h(float a, float b, uint32_t& hi, uint32_t& lo) {
    f16 h0 = __float2half_rn(a);
    f16 h1 = __float2half_rn(b);
    hi = ((uint32_t)__half_as_ushort(h1) << 16) | __half_as_ushort(h0);
    lo = pack_h2(a - __half2float(h0), b - __half2float(h1));
}

#define CP_ASYNC16(dst, src) \
    asm volatile("cp.async.cg.shared.global [%0], [%1], 16;" :: "r"(dst), "l"(src))
#define CP_COMMIT() asm volatile("cp.async.commit_group;" ::: "memory")
#define CP_WAIT(n)  asm volatile("cp.async.wait_group %0;" :: "n"(n) : "memory")

#define LDSM_X4(r0, r1, r2, r3, addr) \
    asm volatile("ldmatrix.sync.aligned.m8n8.x4.shared.b16 {%0,%1,%2,%3}, [%4];" \
                 : "=r"(r0), "=r"(r1), "=r"(r2), "=r"(r3) : "r"(addr))
#define LDSM_X4T(r0, r1, r2, r3, addr) \
    asm volatile("ldmatrix.sync.aligned.m8n8.x4.trans.shared.b16 {%0,%1,%2,%3}, [%4];" \
                 : "=r"(r0), "=r"(r1), "=r"(r2), "=r"(r3) : "r"(addr))

#define MMA16816(d, a, b0, b1) \
    asm volatile("mma.sync.aligned.m16n8k16.row.col.f32.f16.f16.f32 " \
                 "{%0,%1,%2,%3}, {%4,%5,%6,%7}, {%8,%9}, {%0,%1,%2,%3};" \
                 : "+f"((d)[0]), "+f"((d)[1]), "+f"((d)[2]), "+f"((d)[3]) \
                 : "r"((a)[0]), "r"((a)[1]), "r"((a)[2]), "r"((a)[3]), \
                   "r"(b0), "r"(b1))

// ============================================================================
// split kernel: fp32 -> f16 hi + f16 lo (residual)
// ============================================================================
__global__ __launch_bounds__(256) void split_kernel(
    const float4* __restrict__ in, uint2* __restrict__ hi,
    uint2* __restrict__ lo, int n4)
{
    int i = blockIdx.x * 256 + threadIdx.x;
    if (i >= n4) return;
    float4 f = in[i];
    uint32_t h0, l0, h1, l1;
    split2h(f.x, f.y, h0, l0);
    split2h(f.z, f.w, h1, l1);
    hi[i] = make_uint2(h0, h1);
    lo[i] = make_uint2(l0, l1);
}

// quant kernel: fp32 -> single f16 (weights)
__global__ __launch_bounds__(256) void quant_kernel(
    const float4* __restrict__ in, uint2* __restrict__ hi, int n4)
{
    int i = blockIdx.x * 256 + threadIdx.x;
    if (i >= n4) return;
    float4 f = in[i];
    hi[i] = make_uint2(pack_h2(f.x, f.y), pack_h2(f.z, f.w));
}

// ============================================================================
// wm kernel: wm = mask ? exp(-4 d^2) : -1
// ============================================================================
__global__ __launch_bounds__(256) void wm_kernel(
    const int2* __restrict__ mask, const float2* __restrict__ dist,
    float2* __restrict__ wm, int n2)
{
    int i = blockIdx.x * 256 + threadIdx.x;
    if (i >= n2) return;
    int2 m = mask[i];
    float2 d = dist[i];
    float2 w;
    w.x = m.x ? __expf(-4.0f * d.x * d.x) : -1.0f;
    w.y = m.y ? __expf(-4.0f * d.y * d.y) : -1.0f;
    wm[i] = w;
}

// ============================================================================
// fp16 2-mma GEMM via mma.sync.m16n8k16, 3-stage cp.async pipeline.
//   C = sum_n (A_n_hi + A_n_lo) @ W_n_hi + sum_n bias_n[N]
// outmode 0: fp32 to C.  1: f16 hi/lo to Chi/Clo.  2: single f16 to Chi.
// ============================================================================
#define ASTR 72
#define WSTR 136
#define BKC  64
#define A_BYTES (128 * ASTR * 2)                   // 18432
#define W_BYTES (64 * WSTR * 2)                    // 17408
#define BUF_BYTES (2 * A_BYTES + W_BYTES)          // 54272
#define SMB_BUF 1024
#define GEMM_SMEM (SMB_BUF + 3 * BUF_BYTES)        // 163840

__device__ __forceinline__ void load_chunk(
    uint32_t sbuf, const f16* __restrict__ Ah, const f16* __restrict__ Al,
    const f16* __restrict__ Wh, int bm, int bn, int k0, int tid)
{
    #pragma unroll
    for (int v = 0; v < 4; v++) {
        int idx = tid + v * 256;
        int r = idx >> 3, c = idx & 7;
        size_t go = (size_t)(bm + r) * C_ + k0 + c * 8;
        uint32_t so = sbuf + r * (ASTR * 2) + c * 16;
        CP_ASYNC16(so, Ah + go);
        CP_ASYNC16(so + A_BYTES, Al + go);
    }
    #pragma unroll
    for (int v = 0; v < 4; v++) {
        int idx = tid + v * 256;
        int r = idx >> 4, c = idx & 15;
        size_t go = (size_t)(k0 + r) * C_ + bn + c * 8;
        uint32_t so = sbuf + 2 * A_BYTES + r * (WSTR * 2) + c * 16;
        CP_ASYNC16(so, Wh + go);
    }
}

__device__ __forceinline__ void compute_chunk(
    uint32_t sbuf, int wm_, int wn, int lane, float acc[4][4][4])
{
    const uint32_t smAh = sbuf;
    const uint32_t smAl = sbuf + A_BYTES;
    const uint32_t smWh = sbuf + 2 * A_BYTES;
    const int m0 = wm_ * 64, n0 = wn * 32;
    const int ar = lane & 15;
    const int ac = (lane >> 4) << 3;

    #pragma unroll
    for (int ks = 0; ks < 4; ks++) {
        const int kk = ks * 16;
        uint32_t ah[4][4], al[4][4], bh[2][4];
        #pragma unroll
        for (int mi = 0; mi < 4; mi++) {
            uint32_t off = ((m0 + mi * 16 + ar) * ASTR + kk + ac) * 2;
            LDSM_X4(ah[mi][0], ah[mi][1], ah[mi][2], ah[mi][3], smAh + off);
            LDSM_X4(al[mi][0], al[mi][1], al[mi][2], al[mi][3], smAl + off);
        }
        #pragma unroll
        for (int nj = 0; nj < 2; nj++) {
            uint32_t off = ((kk + ar) * WSTR + n0 + nj * 16 +
                            ((lane >> 4) & 1) * 8) * 2;
            LDSM_X4T(bh[nj][0], bh[nj][1], bh[nj][2], bh[nj][3], smWh + off);
        }
        #pragma unroll
        for (int mi = 0; mi < 4; mi++)
            #pragma unroll
            for (int nj = 0; nj < 2; nj++) {
                MMA16816(acc[mi][nj * 2],     ah[mi], bh[nj][0], bh[nj][1]);
                MMA16816(acc[mi][nj * 2],     al[mi], bh[nj][0], bh[nj][1]);
                MMA16816(acc[mi][nj * 2 + 1], ah[mi], bh[nj][2], bh[nj][3]);
                MMA16816(acc[mi][nj * 2 + 1], al[mi], bh[nj][2], bh[nj][3]);
            }
    }
}

__global__ __launch_bounds__(256) void gemm_mma_kernel(
    const f16* __restrict__ Ah, const f16* __restrict__ Al,
    const f16* __restrict__ Wh,
    const float* __restrict__ bias, float* __restrict__ C,
    f16* __restrict__ Chi, f16* __restrict__ Clo,
    int nmat, size_t strideA, size_t strideW, int outmode)
{
    extern __shared__ char smc[];
    const uint32_t smb = smem_u32(smc);
    float* s_bias = (float*)smc;

    const int tid = threadIdx.x;
    const int lane = tid & 31;
    const int wid = tid >> 5;
    const int wm_ = wid & 1;
    const int wn = wid >> 1;
    const int bm = blockIdx.y * 128;
    const int bn = blockIdx.x * 128;

    if (tid < 128) {
        float bs = 0.f;
        for (int n = 0; n < nmat; n++) bs += bias[(size_t)n * C_ + bn + tid];
        s_bias[tid] = bs;
    }

    float acc[4][4][4];
    #pragma unroll
    for (int mi = 0; mi < 4; mi++)
        #pragma unroll
        for (int ni = 0; ni < 4; ni++)
            #pragma unroll
            for (int r = 0; r < 4; r++) acc[mi][ni][r] = 0.f;

    const int NC = nmat * (C_ / BKC);

    // prologue: chunks 0, 1
    load_chunk(smb + SMB_BUF, Ah, Al, Wh, bm, bn, 0, tid);
    CP_COMMIT();
    load_chunk(smb + SMB_BUF + BUF_BYTES, Ah, Al, Wh, bm, bn, BKC, tid);
    CP_COMMIT();

    for (int c = 0; c < NC; c++) {
        if (c + 1 < NC) { CP_WAIT(1); } else { CP_WAIT(0); }
        __syncthreads();
        if (c + 2 < NC) {
            int cc = c + 2;
            int nm = cc >> 4;
            int k0 = (cc & 15) * BKC;
            load_chunk(smb + SMB_BUF + (cc % 3) * BUF_BYTES,
                       Ah + (size_t)nm * strideA, Al + (size_t)nm * strideA,
                       Wh + (size_t)nm * strideW, bm, bn, k0, tid);
            CP_COMMIT();
        }
        compute_chunk(smb + SMB_BUF + (c % 3) * BUF_BYTES, wm_, wn, lane, acc);
    }

    const int r0 = bm + wm_ * 64 + (lane >> 2);
    const int c0rel = wn * 32 + 2 * (lane & 3);
    #pragma unroll
    for (int mi = 0; mi < 4; mi++) {
        #pragma unroll
        for (int ni = 0; ni < 4; ni++) {
            int crel = c0rel + ni * 8;
            float b0 = s_bias[crel], b1 = s_bias[crel + 1];
            int row = r0 + mi * 16;
            float a0 = acc[mi][ni][0] + b0, a1 = acc[mi][ni][1] + b1;
            float a2 = acc[mi][ni][2] + b0, a3 = acc[mi][ni][3] + b1;
            if (outmode == 0) {
                *(float2*)&C[(size_t)row * C_ + bn + crel] = make_float2(a0, a1);
                *(float2*)&C[(size_t)(row + 8) * C_ + bn + crel] = make_float2(a2, a3);
            } else if (outmode == 1) {
                uint32_t h0, l0, h1, l1;
                split2h(a0, a1, h0, l0);
                split2h(a2, a3, h1, l1);
                *(uint32_t*)&Chi[(size_t)row * C_ + bn + crel] = h0;
                *(uint32_t*)&Clo[(size_t)row * C_ + bn + crel] = l0;
                *(uint32_t*)&Chi[(size_t)(row + 8) * C_ + bn + crel] = h1;
                *(uint32_t*)&Clo[(size_t)(row + 8) * C_ + bn + crel] = l1;
            } else {
                *(uint32_t*)&Chi[(size_t)row * C_ + bn + crel] = pack_h2(a0, a1);
                *(uint32_t*)&Chi[(size_t)(row + 8) * C_ + bn + crel] = pack_h2(a2, a3);
            }
        }
    }
}

// ============================================================================
// Flash attention: fp16 2-mma, register softmax, precomputed wm, 3-stage KV.
// Q and P are the exact (hi/lo) side; K and V are single-f16 quantized.
// CTA: 128 q-rows, kv chunks of 64, 8 warps (16 q-rows each).
// ============================================================================
#define FQ 128
#define FS 64
#define FSTR 72
#define OFF_QH 0
#define OFF_QL 18432
#define OFF_BUF 36864
#define KV_BUF_BYTES 18432                         // K 9216 + V 9216
#define FLASH_SMEM (OFF_BUF + 3 * KV_BUF_BYTES)    // 92160

__device__ __forceinline__ void flash_load_kv(
    uint32_t bb, const f16* __restrict__ Kh, const f16* __restrict__ Vh,
    int b, int h, int s0, int tid)
{
    #pragma unroll
    for (int v = 0; v < 2; v++) {
        int idx = tid + v * 256;
        int r = idx >> 3, c = idx & 7;
        size_t go = (size_t)(b * T_ + s0 + r) * C_ + h * HD_ + c * 8;
        uint32_t so = bb + r * (FSTR * 2) + c * 16;
        CP_ASYNC16(so,        Kh + go);
        CP_ASYNC16(so + 9216, Vh + go);
    }
}

__global__ __launch_bounds__(256) void flash_mma_kernel(
    const f16* __restrict__ Qh, const f16* __restrict__ Ql,
    const f16* __restrict__ Kh, const f16* __restrict__ Vh,
    const float* __restrict__ wm, f16* __restrict__ Ohi,
    f16* __restrict__ Olo)
{
    extern __shared__ char smc[];
    const uint32_t smb = smem_u32(smc);

    const int bh  = blockIdx.x;
    const int b   = bh >> 4;
    const int h   = bh & 15;
    const int t10 = blockIdx.y * FQ;
    const int tid = threadIdx.x;
    const int lane = tid & 31;
    const int wid = tid >> 5;
    const int m0 = wid * 16;
    const int g  = lane >> 2;
    const int c2 = (lane & 3) * 2;

    const int qr0 = t10 + m0 + g;
    const int qr1 = qr0 + 8;
    const float* wrow0 = &wm[(size_t)(b * T_ + qr0) * T_];
    const float* wrow1 = &wm[(size_t)(b * T_ + qr1) * T_];

    // ---- load Q tile (hi/lo) ----
    #pragma unroll
    for (int v = 0; v < 4; v++) {
        int idx = tid + v * 256;
        int r = idx >> 3, c = idx & 7;
        size_t go = (size_t)(b * T_ + t10 + r) * C_ + h * HD_ + c * 8;
        uint32_t so = smb + r * (FSTR * 2) + c * 16;
        CP_ASYNC16(so + OFF_QH, Qh + go);
        CP_ASYNC16(so + OFF_QL, Ql + go);
    }
    CP_COMMIT();
    // ---- kv chunks 0, 1 ----
    flash_load_kv(smb + OFF_BUF, Kh, Vh, b, h, 0, tid);
    CP_COMMIT();
    flash_load_kv(smb + OFF_BUF + KV_BUF_BYTES, Kh, Vh, b, h, FS, tid);
    CP_COMMIT();

    float mstat0 = -3.0e38f, mstat1 = -3.0e38f;
    float lstat0 = 0.f, lstat1 = 0.f;

    float oacc[8][4];
    #pragma unroll
    for (int ni = 0; ni < 8; ni++)
        #pragma unroll
        for (int r = 0; r < 4; r++) oacc[ni][r] = 0.f;

    const int NITER = T_ / FS;           // 32

    for (int it = 0; it < NITER; it++) {
        if (it + 1 < NITER) { CP_WAIT(1); } else { CP_WAIT(0); }
        __syncthreads();
        if (it + 2 < NITER) {
            flash_load_kv(smb + OFF_BUF + ((it + 2) % 3) * KV_BUF_BYTES,
                          Kh, Vh, b, h, (it + 2) * FS, tid);
            CP_COMMIT();
        }

        const int s0 = it * FS;
        const uint32_t bb = smb + OFF_BUF + (it % 3) * KV_BUF_BYTES;
        const uint32_t smKh = bb;
        const uint32_t smVh = bb + 9216;

        // ---- S = (Qh + Ql) K^T ----
        float sacc[8][4];
        #pragma unroll
        for (int ni = 0; ni < 8; ni++)
            #pragma unroll
            for (int r = 0; r < 4; r++) sacc[ni][r] = 0.f;

        #pragma unroll
        for (int ks = 0; ks < 4; ks++) {
            const int k0 = ks * 16;
            uint32_t qh[4], ql[4];
            uint32_t aoff = ((m0 + (lane & 15)) * FSTR + k0 + ((lane >> 4) << 3)) * 2;
            LDSM_X4(qh[0], qh[1], qh[2], qh[3], smb + OFF_QH + aoff);
            LDSM_X4(ql[0], ql[1], ql[2], ql[3], smb + OFF_QL + aoff);
            #pragma unroll
            for (int nj = 0; nj < 4; nj++) {
                uint32_t kh4[4];
                uint32_t boff = ((nj * 16 + (lane & 7) + ((lane >> 4) << 3)) * FSTR +
                                 k0 + ((lane >> 3) & 1) * 8) * 2;
                LDSM_X4(kh4[0], kh4[1], kh4[2], kh4[3], smKh + boff);
                MMA16816(sacc[nj * 2],     qh, kh4[0], kh4[1]);
                MMA16816(sacc[nj * 2],     ql, kh4[0], kh4[1]);
                MMA16816(sacc[nj * 2 + 1], qh, kh4[2], kh4[3]);
                MMA16816(sacc[nj * 2 + 1], ql, kh4[2], kh4[3]);
            }
        }

        // ---- wm load: scale + mask via sign ----
        float wreg[8][4];
        #pragma unroll
        for (int ni = 0; ni < 8; ni++) {
            int s = s0 + ni * 8 + c2;
            float2 w0 = *(const float2*)&wrow0[s];
            float2 w1 = *(const float2*)&wrow1[s];
            wreg[ni][0] = w0.x; wreg[ni][1] = w0.y;
            wreg[ni][2] = w1.x; wreg[ni][3] = w1.y;
            sacc[ni][0] = w0.x > 0.f ? sacc[ni][0] * 0.125f : NEG_;
            sacc[ni][1] = w0.y > 0.f ? sacc[ni][1] * 0.125f : NEG_;
            sacc[ni][2] = w1.x > 0.f ? sacc[ni][2] * 0.125f : NEG_;
            sacc[ni][3] = w1.y > 0.f ? sacc[ni][3] * 0.125f : NEG_;
        }

        // ---- row max ----
        float mx0 = -3.0e38f, mx1 = -3.0e38f;
        #pragma unroll
        for (int ni = 0; ni < 8; ni++) {
            mx0 = fmaxf(mx0, fmaxf(sacc[ni][0], sacc[ni][1]));
            mx1 = fmaxf(mx1, fmaxf(sacc[ni][2], sacc[ni][3]));
        }
        mx0 = fmaxf(mx0, __shfl_xor_sync(0xffffffff, mx0, 1));
        mx0 = fmaxf(mx0, __shfl_xor_sync(0xffffffff, mx0, 2));
        mx1 = fmaxf(mx1, __shfl_xor_sync(0xffffffff, mx1, 1));
        mx1 = fmaxf(mx1, __shfl_xor_sync(0xffffffff, mx1, 2));

        float mnew0 = fmaxf(mstat0, mx0);
        float mnew1 = fmaxf(mstat1, mx1);
        float fr0 = __expf(mstat0 - mnew0);
        float fr1 = __expf(mstat1 - mnew1);
        mstat0 = mnew0; mstat1 = mnew1;

        // ---- exp + row sum ----
        float sum0 = 0.f, sum1 = 0.f;
        #pragma unroll
        for (int ni = 0; ni < 8; ni++) {
            sacc[ni][0] = __expf(sacc[ni][0] - mnew0);
            sacc[ni][1] = __expf(sacc[ni][1] - mnew0);
            sacc[ni][2] = __expf(sacc[ni][2] - mnew1);
            sacc[ni][3] = __expf(sacc[ni][3] - mnew1);
            sum0 += sacc[ni][0] + sacc[ni][1];
            sum1 += sacc[ni][2] + sacc[ni][3];
        }
        sum0 += __shfl_xor_sync(0xffffffff, sum0, 1);
        sum0 += __shfl_xor_sync(0xffffffff, sum0, 2);
        sum1 += __shfl_xor_sync(0xffffffff, sum1, 1);
        sum1 += __shfl_xor_sync(0xffffffff, sum1, 2);
        lstat0 = lstat0 * fr0 + sum0;
        lstat1 = lstat1 * fr1 + sum1;

        // ---- numerator modulation + pack P fragments (hi/lo, exact) ----
        uint32_t aH[4][4], aL[4][4];
        #pragma unroll
        for (int j = 0; j < 4; j++) {
            #pragma unroll
            for (int half = 0; half < 2; half++) {
                int ni = 2 * j + half;
                float p00 = sacc[ni][0] * wreg[ni][0];
                float p01 = sacc[ni][1] * wreg[ni][1];
                float p10 = sacc[ni][2] * wreg[ni][2];
                float p11 = sacc[ni][3] * wreg[ni][3];
                split2h(p00, p01, aH[j][half * 2 + 0], aL[j][half * 2 + 0]);
                split2h(p10, p11, aH[j][half * 2 + 1], aL[j][half * 2 + 1]);
            }
        }

        // ---- rescale O, then O += (Ph + Pl) @ V ----
        #pragma unroll
        for (int ni = 0; ni < 8; ni++) {
            oacc[ni][0] *= fr0; oacc[ni][1] *= fr0;
            oacc[ni][2] *= fr1; oacc[ni][3] *= fr1;
        }
        #pragma unroll
        for (int j = 0; j < 4; j++) {
            #pragma unroll
            for (int nj = 0; nj < 4; nj++) {
                uint32_t vh4[4];
                uint32_t boff = ((j * 16 + (lane & 15)) * FSTR +
                                 (nj * 2 + ((lane >> 4) & 1)) * 8) * 2;
                LDSM_X4T(vh4[0], vh4[1], vh4[2], vh4[3], smVh + boff);
                MMA16816(oacc[nj * 2],     aH[j], vh4[0], vh4[1]);
                MMA16816(oacc[nj * 2],     aL[j], vh4[0], vh4[1]);
                MMA16816(oacc[nj * 2 + 1], aH[j], vh4[2], vh4[3]);
                MMA16816(oacc[nj * 2 + 1], aL[j], vh4[2], vh4[3]);
            }
        }
    }

    // ---- epilogue: /l, write f16 hi/lo ----
    {
        float inv0 = 1.0f / lstat0;
        float inv1 = 1.0f / lstat1;
        size_t row0 = (size_t)(b * T_ + qr0) * C_ + h * HD_;
        size_t row1 = (size_t)(b * T_ + qr1) * C_ + h * HD_;
        #pragma unroll
        for (int ni = 0; ni < 8; ni++) {
            int c = ni * 8 + c2;
            uint32_t h0, l0, h1, l1;
            split2h(oacc[ni][0] * inv0, oacc[ni][1] * inv0, h0, l0);
            split2h(oacc[ni][2] * inv1, oacc[ni][3] * inv1, h1, l1);
            *(uint32_t*)&Ohi[row0 + c] = h0;
            *(uint32_t*)&Olo[row0 + c] = l0;
            *(uint32_t*)&Ohi[row1 + c] = h1;
            *(uint32_t*)&Olo[row1 + c] = l1;
        }
    }
}

// ============================================================================
// Launch
// ============================================================================
extern "C" void kernel_launch(void* const* d_in, const int* in_sizes, int n_in,
                              void* d_out, int out_size)
{
    const float* x_q  = (const float*)d_in[0];
    const float* x_r  = (const float*)d_in[1];
    const float* y    = (const float*)d_in[2];
    const int*   mask = (const int*)  d_in[3];
    const float* dist = (const float*)d_in[4];
    const float* Wq   = (const float*)d_in[5];
    const float* bq   = (const float*)d_in[6];
    const float* Wk   = (const float*)d_in[7];
    const float* bk   = (const float*)d_in[8];
    const float* Wv   = (const float*)d_in[9];
    const float* bv   = (const float*)d_in[10];
    const float* Wp   = (const float*)d_in[11];
    const float* bp   = (const float*)d_in[12];
    float* out = (float*)d_out;

    f16 *qh, *ql, *kh, *vh;
    f16 *xqh, *xql, *xrh, *xrl, *yh, *yl, *Oh, *Ol;
    f16 *wqh, *wkh, *wvh, *wph;
    float* wmp;
    cudaGetSymbolAddress((void**)&qh,  g_Qh);
    cudaGetSymbolAddress((void**)&ql,  g_Ql);
    cudaGetSymbolAddress((void**)&kh,  g_Kh);
    cudaGetSymbolAddress((void**)&vh,  g_Vh);
    cudaGetSymbolAddress((void**)&xqh, g_xqh);
    cudaGetSymbolAddress((void**)&xql, g_xql);
    cudaGetSymbolAddress((void**)&xrh, g_xrh);
    cudaGetSymbolAddress((void**)&xrl, g_xrl);
    cudaGetSymbolAddress((void**)&yh,  g_yh);
    cudaGetSymbolAddress((void**)&yl,  g_yl);
    cudaGetSymbolAddress((void**)&Oh,  g_Oh);
    cudaGetSymbolAddress((void**)&Ol,  g_Ol);
    cudaGetSymbolAddress((void**)&wqh, g_Wqh);
    cudaGetSymbolAddress((void**)&wkh, g_Wkh);
    cudaGetSymbolAddress((void**)&wvh, g_Wvh);
    cudaGetSymbolAddress((void**)&wph, g_Wph);
    cudaGetSymbolAddress((void**)&wmp, g_wm);

    cudaFuncSetAttribute(gemm_mma_kernel,
                         cudaFuncAttributeMaxDynamicSharedMemorySize, GEMM_SMEM);
    cudaFuncSetAttribute(flash_mma_kernel,
                         cudaFuncAttributeMaxDynamicSharedMemorySize, FLASH_SMEM);

    // ---- split activations (hi/lo), quantize weights (single), build wm ----
    const int MC4 = M_ * C_ / 4;
    const int CC4 = C_ * C_ / 4;
    split_kernel<<<MC4 / 256, 256>>>((const float4*)x_q, (uint2*)xqh, (uint2*)xql, MC4);
    split_kernel<<<MC4 / 256, 256>>>((const float4*)x_r, (uint2*)xrh, (uint2*)xrl, MC4);
    split_kernel<<<NI_ * MC4 / 256, 256>>>((const float4*)y, (uint2*)yh, (uint2*)yl, NI_ * MC4);
    quant_kernel<<<CC4 / 256, 256>>>((const float4*)Wq, (uint2*)wqh, CC4);
    quant_kernel<<<CC4 / 256, 256>>>((const float4*)Wk, (uint2*)wkh, CC4);
    quant_kernel<<<NI_ * CC4 / 256, 256>>>((const float4*)Wv, (uint2*)wvh, NI_ * CC4);
    quant_kernel<<<CC4 / 256, 256>>>((const float4*)Wp, (uint2*)wph, CC4);
    {
        const int n2 = B_ * T_ * T_ / 2;
        wm_kernel<<<(n2 + 255) / 256, 256>>>((const int2*)mask,
                                             (const float2*)dist,
                                             (float2*)wmp, n2);
    }

    dim3 gblk(256);
    dim3 ggrd(C_ / 128, M_ / 128);

    // projections: Q -> hi/lo, K -> single, V -> single
    gemm_mma_kernel<<<ggrd, gblk, GEMM_SMEM>>>(xqh, xql, wqh, bq,
                                               nullptr, qh, ql, 1, 0, 0, 1);
    gemm_mma_kernel<<<ggrd, gblk, GEMM_SMEM>>>(xrh, xrl, wkh, bk,
                                               nullptr, kh, nullptr, 1, 0, 0, 2);
    gemm_mma_kernel<<<ggrd, gblk, GEMM_SMEM>>>(yh, yl, wvh, bv,
                                               nullptr, vh, nullptr, NI_,
                                               (size_t)M_ * C_, (size_t)C_ * C_, 2);

    dim3 fgrd(B_ * H_, T_ / FQ);         // (32, 16)
    flash_mma_kernel<<<fgrd, 256, FLASH_SMEM>>>(qh, ql, kh, vh, wmp, Oh, Ol);

    // out projection -> fp32
    gemm_mma_kernel<<<ggrd, gblk, GEMM_SMEM>>>(Oh, Ol, wph, bp,
                                               out, nullptr, nullptr, 1, 0, 0, 0);
}